// round 15
// baseline (speedup 1.0000x reference)
#include <cuda_runtime.h>
#include <cuda_fp16.h>
#include <math.h>
#include <stdint.h>

// Problem dims (fixed by the dataset)
#define B_   4
#define N_   512
#define C_   1024
#define HID_ 4096
#define NH_  16
#define D_   64
#define R_   (B_*N_)     // 2048 rows per stream
#define R2_  (2*R_)      // 4096 rows: x-stream and y-stream batched
#define EPS_ 1e-5f

// ---------------- scratch (device globals: no allocation allowed) ----------
__device__ float g_zb[R2_*C_];    // concat(x, y) residual stream
// fp16 fragment buffers for attention (written by lnq_kernel)
__device__ uint32_t g_qf[R2_*C_/2];     // Q A-frags (scaled 1/8), per (16-row tile, head)
__device__ uint32_t g_kf[R2_*C_/2];     // K B-frags, per (8-row ntile, head)
__device__ uint32_t g_vf[R2_*C_/2];     // V B-frags, per (16-row vtile, head)
// fp16-packed (A-fragment layout) activations
__device__ uint32_t g_obh[R2_*C_/2];    // fattn out -> proj A
__device__ uint32_t g_n2h[R2_*C_/2];    // ln2 out   -> fc1 A
__device__ uint32_t g_hbh[R2_*HID_/2];  // gelu out  -> fc2 A
// fp16 weights packed in mma.m16n8k16 B-fragment layout
__device__ uint32_t g_pwh[C_*C_/2];
__device__ uint32_t g_w1h[C_*HID_/2];
__device__ uint32_t g_w2h[HID_*C_/2];

// ======================= helpers =======================
#define CP_ASYNC16(sm, gp) \
    asm volatile("cp.async.cg.shared.global [%0], [%1], 16;" :: "r"(sm), "l"(gp))
#define CP_COMMIT() asm volatile("cp.async.commit_group;" ::: "memory")
#define CP_WAIT0()  asm volatile("cp.async.wait_group 0;" ::: "memory")
#define CP_WAIT1()  asm volatile("cp.async.wait_group 1;" ::: "memory")

__device__ __forceinline__ uint32_t smem_u32(const void* p) {
    uint32_t a;
    asm("{ .reg .u64 t; cvta.to.shared.u64 t, %1; cvt.u32.u64 %0, t; }" : "=r"(a) : "l"(p));
    return a;
}

__device__ __forceinline__ uint32_t packh2(float a, float b) {
    __half2 h = __halves2half2(__float2half_rn(a), __float2half_rn(b));
    return *(uint32_t*)&h;
}

__device__ __forceinline__ void mma_f16(float* c, const uint32_t* a, const uint32_t* b) {
    asm volatile(
        "mma.sync.aligned.m16n8k16.row.col.f32.f16.f16.f32 "
        "{%0,%1,%2,%3}, {%4,%5,%6,%7}, {%8,%9}, {%0,%1,%2,%3};"
        : "+f"(c[0]), "+f"(c[1]), "+f"(c[2]), "+f"(c[3])
        : "r"(a[0]), "r"(a[1]), "r"(a[2]), "r"(a[3]), "r"(b[0]), "r"(b[1]));
}

__device__ __forceinline__ float fast_exp(float x) {
    float tt = fmaxf(x * 1.4426950408889634f, -126.0f);
    float fi = floorf(tt);
    float f = tt - fi;
    float p = 0.0013333558f;
    p = fmaf(p, f, 0.0096181291f);
    p = fmaf(p, f, 0.0555041087f);
    p = fmaf(p, f, 0.2402265070f);
    p = fmaf(p, f, 0.6931471806f);
    p = fmaf(p, f, 1.0f);
    return p * __int_as_float((__float2int_rn(fi) + 127) << 23);
}

// ===== LN1 -> Q/K/V fp16 fragment buffers (16 rows = 1 q/v tile, 2 k tiles) =
__global__ void __launch_bounds__(256) lnq_kernel(
    const float* __restrict__ in, uint32_t* __restrict__ qf,
    uint32_t* __restrict__ kf, uint32_t* __restrict__ vf,
    const float* __restrict__ gm, const float* __restrict__ bt,
    const int* guard)
{
    if (guard && !guard[0]) return;
    __shared__ uint32_t sh[8192];   // 32KB staging, reused 3x
    const int tid = threadIdx.x;
    const int w = tid >> 5, lane = tid & 31;
    const int row0 = blockIdx.x * 16 + w * 2;
    const float* x0 = in + (size_t)row0 * C_;
    const float* x1 = x0 + C_;

    float4 v0[8], v1[8];
    float s0 = 0.f, q0 = 0.f, s1 = 0.f, q1 = 0.f;
    #pragma unroll
    for (int i = 0; i < 8; i++) {
        v0[i] = *(const float4*)(x0 + i * 128 + lane * 4);
        s0 += v0[i].x + v0[i].y + v0[i].z + v0[i].w;
        q0 += v0[i].x * v0[i].x + v0[i].y * v0[i].y + v0[i].z * v0[i].z + v0[i].w * v0[i].w;
        v1[i] = *(const float4*)(x1 + i * 128 + lane * 4);
        s1 += v1[i].x + v1[i].y + v1[i].z + v1[i].w;
        q1 += v1[i].x * v1[i].x + v1[i].y * v1[i].y + v1[i].z * v1[i].z + v1[i].w * v1[i].w;
    }
    #pragma unroll
    for (int o = 16; o; o >>= 1) {
        s0 += __shfl_xor_sync(0xffffffffu, s0, o);
        q0 += __shfl_xor_sync(0xffffffffu, q0, o);
        s1 += __shfl_xor_sync(0xffffffffu, s1, o);
        q1 += __shfl_xor_sync(0xffffffffu, q1, o);
    }
    const float mn0 = s0 * (1.0f / C_);
    const float rs0 = rsqrtf(q0 * (1.0f / C_) - mn0 * mn0 + EPS_);
    const float mn1 = s1 * (1.0f / C_);
    const float rs1 = rsqrtf(q1 * (1.0f / C_) - mn1 * mn1 + EPS_);

    const int ag0 = row0 & 7;
    const int arm = (row0 >> 3) & 1;

    // ---- pass 1: Q A-fragments (scaled 1/8) ----
    #pragma unroll
    for (int i = 0; i < 8; i++) {
        int c = i * 128 + lane * 4;
        int h = c >> 6, d = c & 63;
        float4 gv = *(const float4*)(gm + c);
        float4 bv = *(const float4*)(bt + c);
        int kt = d >> 4;
        int tt = (d & 7) >> 1;
        int rk = (d & 15) >> 3;
        int bq = h * 512 + (kt * 32 + tt) * 4 + arm + 2 * rk;
        float a0 = ((v0[i].x - mn0) * rs0 * gv.x + bv.x) * 0.125f;
        float a1 = ((v0[i].y - mn0) * rs0 * gv.y + bv.y) * 0.125f;
        float a2 = ((v0[i].z - mn0) * rs0 * gv.z + bv.z) * 0.125f;
        float a3 = ((v0[i].w - mn0) * rs0 * gv.w + bv.w) * 0.125f;
        sh[bq + ag0 * 16] = packh2(a0, a1);
        sh[bq + ag0 * 16 + 4] = packh2(a2, a3);
        float c0 = ((v1[i].x - mn1) * rs1 * gv.x + bv.x) * 0.125f;
        float c1 = ((v1[i].y - mn1) * rs1 * gv.y + bv.y) * 0.125f;
        float c2 = ((v1[i].z - mn1) * rs1 * gv.z + bv.z) * 0.125f;
        float c3 = ((v1[i].w - mn1) * rs1 * gv.w + bv.w) * 0.125f;
        sh[bq + (ag0 + 1) * 16] = packh2(c0, c1);
        sh[bq + (ag0 + 1) * 16 + 4] = packh2(c2, c3);
    }
    __syncthreads();
    {
        size_t gb = (size_t)blockIdx.x * 8192;
        #pragma unroll
        for (int q = 0; q < 8; q++) {
            int i = q * 256 + tid;
            *(uint4*)(qf + gb + (size_t)i * 4) = ((const uint4*)sh)[i];
        }
    }
    __syncthreads();

    // ---- pass 2: K B-fragments (unscaled) ----
    {
        const int ntl = (row0 >> 3) & 1;
        #pragma unroll
        for (int i = 0; i < 8; i++) {
            int c = i * 128 + lane * 4;
            int h = c >> 6, d = c & 63;
            float4 gv = *(const float4*)(gm + c);
            float4 bv = *(const float4*)(bt + c);
            int kt = d >> 4;
            int lf = (d & 7) >> 1;
            int reg = (d & 15) >> 3;
            int bk0 = (ntl * 16 + h) * 256 + kt * 64 + reg;
            float a0 = (v0[i].x - mn0) * rs0 * gv.x + bv.x;
            float a1 = (v0[i].y - mn0) * rs0 * gv.y + bv.y;
            float a2 = (v0[i].z - mn0) * rs0 * gv.z + bv.z;
            float a3 = (v0[i].w - mn0) * rs0 * gv.w + bv.w;
            sh[bk0 + (ag0 * 4 + lf) * 2] = packh2(a0, a1);
            sh[bk0 + (ag0 * 4 + lf + 1) * 2] = packh2(a2, a3);
            float c0 = (v1[i].x - mn1) * rs1 * gv.x + bv.x;
            float c1 = (v1[i].y - mn1) * rs1 * gv.y + bv.y;
            float c2 = (v1[i].z - mn1) * rs1 * gv.z + bv.z;
            float c3 = (v1[i].w - mn1) * rs1 * gv.w + bv.w;
            sh[bk0 + ((ag0 + 1) * 4 + lf) * 2] = packh2(c0, c1);
            sh[bk0 + ((ag0 + 1) * 4 + lf + 1) * 2] = packh2(c2, c3);
        }
    }
    __syncthreads();
    {
        size_t gb = (size_t)blockIdx.x * 8192;
        #pragma unroll
        for (int q = 0; q < 8; q++) {
            int i = q * 256 + tid;
            *(uint4*)(kf + gb + (size_t)i * 4) = ((const uint4*)sh)[i];
        }
    }
    __syncthreads();

    // ---- pass 3: V B-fragments (pairs across rows) ----
    {
        const int spw = w;
        const int reg = (spw >> 2) & 1;
        const int lt = spw & 3;
        #pragma unroll
        for (int i = 0; i < 8; i++) {
            int c = i * 128 + lane * 4;
            int h = c >> 6, d0 = c & 63;
            float4 gv = *(const float4*)(gm + c);
            float4 bv = *(const float4*)(bt + c);
            float a[4] = {
                (v0[i].x - mn0) * rs0 * gv.x + bv.x,
                (v0[i].y - mn0) * rs0 * gv.y + bv.y,
                (v0[i].z - mn0) * rs0 * gv.z + bv.z,
                (v0[i].w - mn0) * rs0 * gv.w + bv.w };
            float cc[4] = {
                (v1[i].x - mn1) * rs1 * gv.x + bv.x,
                (v1[i].y - mn1) * rs1 * gv.y + bv.y,
                (v1[i].z - mn1) * rs1 * gv.z + bv.z,
                (v1[i].w - mn1) * rs1 * gv.w + bv.w };
            #pragma unroll
            for (int e = 0; e < 4; e++) {
                int d = d0 + e;
                int dnt = d >> 3;
                int lanef = (d & 7) * 4 + lt;
                sh[h * 512 + (dnt * 32 + lanef) * 2 + reg] = packh2(a[e], cc[e]);
            }
        }
    }
    __syncthreads();
    {
        size_t gb = (size_t)blockIdx.x * 8192;
        #pragma unroll
        for (int q = 0; q < 8; q++) {
            int i = q * 256 + tid;
            *(uint4*)(vf + gb + (size_t)i * 4) = ((const uint4*)sh)[i];
        }
    }
}

// ============ LayerNorm -> packed fp16 A-fragments (for ln2 -> fc1) =========
__global__ void __launch_bounds__(256) lnp_kernel(
    const float* __restrict__ in, uint32_t* __restrict__ outH,
    const float* __restrict__ gm, const float* __restrict__ bt,
    const int* guard)
{
    if (guard && !guard[0]) return;
    extern __shared__ __align__(16) char sml[];
    uint32_t* sh = (uint32_t*)sml;
    const int w = threadIdx.x >> 5, lane = threadIdx.x & 31;
    #pragma unroll
    for (int rr = 0; rr < 2; rr++) {
        const int row = blockIdx.x * 16 + w * 2 + rr;
        const float* x = in + (size_t)row * C_;
        float4 v[8];
        float s = 0.f, ss = 0.f;
        #pragma unroll
        for (int i = 0; i < 8; i++) {
            v[i] = *(const float4*)(x + i * 128 + lane * 4);
            s += v[i].x + v[i].y + v[i].z + v[i].w;
            ss += v[i].x * v[i].x + v[i].y * v[i].y + v[i].z * v[i].z + v[i].w * v[i].w;
        }
        #pragma unroll
        for (int o = 16; o; o >>= 1) {
            s  += __shfl_xor_sync(0xffffffffu, s, o);
            ss += __shfl_xor_sync(0xffffffffu, ss, o);
        }
        float mean = s * (1.0f / C_);
        float rstd = rsqrtf(ss * (1.0f / C_) - mean * mean + EPS_);
        const int ag = row & 7, m8 = (row >> 3) & 1;
        const int kin = (lane & 3) * 4;
        const int tt0 = (kin & 7) >> 1, rk = kin >> 3;
        #pragma unroll
        for (int i = 0; i < 8; i++) {
            int c = i * 128 + lane * 4;
            float4 gv = *(const float4*)(gm + c);
            float4 bv = *(const float4*)(bt + c);
            float n0 = (v[i].x - mean) * rstd * gv.x + bv.x;
            float n1 = (v[i].y - mean) * rstd * gv.y + bv.y;
            float n2 = (v[i].z - mean) * rstd * gv.z + bv.z;
            float n3 = (v[i].w - mean) * rstd * gv.w + bv.w;
            int kt = c >> 4;
            int r = m8 + 2 * rk;
            sh[(kt * 32 + ag * 4 + tt0) * 4 + r] = packh2(n0, n1);
            sh[(kt * 32 + ag * 4 + tt0 + 1) * 4 + r] = packh2(n2, n3);
        }
    }
    __syncthreads();
    size_t gbase = (size_t)blockIdx.x * 8192;
    #pragma unroll
    for (int q = 0; q < 8; q++) {
        int i = q * 256 + threadIdx.x;
        *(uint4*)(outH + gbase + (size_t)i * 4) = ((const uint4*)sh)[i];
    }
}

// ========== weight prep: fp16 pack into B-fragment layout =========
__global__ void pack_weight(const float* __restrict__ W, uint32_t* __restrict__ hiP,
                            int K, int N) {
    int warp = threadIdx.x >> 5, lane = threadIdx.x & 31;
    int g = lane >> 2, t = lane & 3;
    int ktiles = K >> 4;
    int tiles = (N >> 3) * ktiles;
    for (int tile = blockIdx.x * 8 + warp; tile < tiles; tile += gridDim.x * 8) {
        int ntg = tile / ktiles, ksg = tile % ktiles;
        int n = ntg * 8 + g;
        #pragma unroll
        for (int reg = 0; reg < 2; reg++) {
            int k = ksg * 16 + 2 * t + reg * 8;
            float x0 = W[(size_t)k * N + n];
            float x1 = W[(size_t)(k + 1) * N + n];
            hiP[((size_t)tile * 32 + lane) * 2 + reg] = packh2(x0, x1);
        }
    }
}

// ========= fp16 mma GEMM: 256x128 CTA tile, 512 threads, 16 warps ==========
// Warp grid 4m x 4n of 64x32 tiles. Stage (24KB): A[0,16K) B[16K,24K).
// 3 stages = 72KB smem, 1 CTA/SM, ~110 regs.
#define GM_STAGE 24576
#define GM_SMEM  (3 * GM_STAGE)

template <int EPI>
__global__ void __launch_bounds__(512) gemm_mma(
    const uint32_t* __restrict__ AP, const uint32_t* __restrict__ BP,
    float* __restrict__ Cout, const float* __restrict__ bias,
    const float* __restrict__ res, uint32_t* __restrict__ OutHi,
    int M, int Nt, int K, const int* guard)
{
    if (guard && !guard[0]) return;
    extern __shared__ __align__(16) char smc[];
    const int tid = threadIdx.x;
    const int warp = tid >> 5, lane = tid & 31;
    const int g = lane >> 2, t = lane & 3;
    const int wm = warp & 3, wn = warp >> 2;
    const int bm = blockIdx.y * 256, bn = blockIdx.x * 128;
    const uint32_t sb = smem_u32(smc);

    const int NIT = K >> 5;
    const int ktiles = K >> 4;
    const int bm16 = bm >> 4, bn8 = bn >> 3;

    auto cpA = [&](int stage, int it) {
        uint32_t dstb = sb + stage * GM_STAGE;
        int kt0 = it * 2;
        #pragma unroll
        for (int q = 0; q < 2; q++) {
            int slot = q * 512 + tid;         // 0..1023
            int chunk = slot >> 5, j = slot & 31;
            int mtl = chunk >> 1, ktl = chunk & 1;
            size_t gidx = (((size_t)(bm16 + mtl) * ktiles + kt0 + ktl) * 32 + j) * 4;
            CP_ASYNC16(dstb + (uint32_t)slot * 16, AP + gidx);
        }
    };
    auto cpB = [&](int stage, int it) {
        uint32_t dstb = sb + stage * GM_STAGE + 16384u;
        int ksg0 = it * 2;
        {
            int slot = tid;                    // 0..511
            int nt = slot >> 5, j = slot & 31;
            size_t srcoff = (((size_t)(bn8 + nt) * ktiles + ksg0) * 64 + (size_t)j * 4);
            CP_ASYNC16(dstb + (uint32_t)slot * 16, BP + srcoff);
        }
    };

    float acc[4][4][4] = {};

    auto compute = [&](int stage) {
        char* base = smc + stage * GM_STAGE;
        #pragma unroll
        for (int ks = 0; ks < 2; ks++) {
            uint32_t ah[4][4], bh[4][2];
            #pragma unroll
            for (int mt = 0; mt < 4; mt++) {
                uint32_t off = (uint32_t)(((wm * 4 + mt) * 2 + ks) * 32 + lane) * 16;
                uint4 v = *(const uint4*)(base + off);
                ah[mt][0] = v.x; ah[mt][1] = v.y; ah[mt][2] = v.z; ah[mt][3] = v.w;
            }
            #pragma unroll
            for (int nt = 0; nt < 4; nt++) {
                uint32_t off = 16384u + (uint32_t)(((wn * 4 + nt) * 2 + ks) * 32 + lane) * 8;
                uint2 v = *(const uint2*)(base + off);
                bh[nt][0] = v.x; bh[nt][1] = v.y;
            }
            #pragma unroll
            for (int mt = 0; mt < 4; mt++)
                #pragma unroll
                for (int nt = 0; nt < 4; nt++)
                    mma_f16(acc[mt][nt], ah[mt], bh[nt]);
        }
    };

    cpA(0, 0); cpB(0, 0); CP_COMMIT();
    cpA(1, 1); cpB(1, 1); CP_COMMIT();

    int st = 0;
    for (int it = 0; it < NIT; it++) {
        if (it + 1 < NIT) { CP_WAIT1(); } else { CP_WAIT0(); }
        __syncthreads();
        if (it + 2 < NIT) {
            int ns = st + 2; if (ns >= 3) ns -= 3;
            cpA(ns, it + 2); cpB(ns, it + 2); CP_COMMIT();
        }
        compute(st);
        if (++st == 3) st = 0;
    }
    __syncthreads();

    if (EPI == 1) {
        #pragma unroll
        for (int mt = 0; mt < 4; mt++) {
            #pragma unroll
            for (int nt = 0; nt < 4; nt++) {
                int row0 = bm + (wm * 4 + mt) * 16 + g;
                int col = bn + wn * 32 + nt * 8 + t * 2;
                float2 bv = *(const float2*)&bias[col];
                float v0 = acc[mt][nt][0] + bv.x;
                float v1 = acc[mt][nt][1] + bv.y;
                float v2 = acc[mt][nt][2] + bv.x;
                float v3 = acc[mt][nt][3] + bv.y;
                size_t i0 = (size_t)row0 * Nt + col;
                size_t i1 = (size_t)(row0 + 8) * Nt + col;
                float2 r0 = *(const float2*)&res[i0];
                float2 r1 = *(const float2*)&res[i1];
                *(float2*)&Cout[i0] = make_float2(v0 + r0.x, v1 + r0.y);
                *(float2*)&Cout[i1] = make_float2(v2 + r1.x, v3 + r1.y);
            }
        }
    } else {
        // GELU -> packed fp16 A-fragments (64KB staged in smem)
        uint32_t* sh = (uint32_t*)smc;
        #pragma unroll
        for (int mt = 0; mt < 4; mt++) {
            #pragma unroll
            for (int nt = 0; nt < 4; nt++) {
                int kl = wn * 32 + nt * 8 + t * 2;
                float2 bv = *(const float2*)&bias[bn + kl];
                float v0 = acc[mt][nt][0] + bv.x;
                float v1 = acc[mt][nt][1] + bv.y;
                float v2 = acc[mt][nt][2] + bv.x;
                float v3 = acc[mt][nt][3] + bv.y;
                v0 = 0.5f * v0 * (1.0f + erff(v0 * 0.70710678118654752f));
                v1 = 0.5f * v1 * (1.0f + erff(v1 * 0.70710678118654752f));
                v2 = 0.5f * v2 * (1.0f + erff(v2 * 0.70710678118654752f));
                v3 = 0.5f * v3 * (1.0f + erff(v3 * 0.70710678118654752f));
                int mtl = wm * 4 + mt;                 // 0..15
                int ktl = kl >> 4;
                int tt = (kl & 7) >> 1;                // == t
                int rk = (kl >> 3) & 1;
                int baseI = ((mtl * 8 + ktl) * 32 + g * 4 + tt) * 4;
                sh[baseI + 2 * rk] = packh2(v0, v1);
                sh[baseI + 1 + 2 * rk] = packh2(v2, v3);
            }
        }
        __syncthreads();
        const int ktO = Nt >> 4;
        #pragma unroll
        for (int q = 0; q < 8; q++) {
            int i = q * 512 + tid;                     // 0..4095 uint4 slots
            int mtl = i >> 8, jj = i & 255;
            size_t gidx = (((size_t)(bm16 + mtl) * ktO + (bn >> 4)) * 128) + (size_t)jj * 4;
            *(uint4*)(OutHi + gidx) = ((const uint4*)sh)[i];
        }
    }
}

// ============ flash attention: pure cp.async fragments + fp16 mma ===========
#define FQ_OFF  0
#define FSTG(st) (16384 + (st) * 32768)
#define FA_SMEM (16384 + 3 * 32768)   // 112KB

__global__ void __launch_bounds__(256, 1) fattn_kernel(
    const uint32_t* __restrict__ qf, const uint32_t* __restrict__ kf,
    const uint32_t* __restrict__ vf, int kvxor,
    uint32_t* __restrict__ Ohi, const int* guard)
{
    if (guard && !guard[0]) return;
    extern __shared__ __align__(16) char smf[];
    const uint32_t sb = smem_u32(smf);
    const int tid = threadIdx.x, lane = tid & 31, warp = tid >> 5;
    const int g = lane >> 2, t = lane & 3;
    const int bh = blockIdx.y, b = bh >> 4, h = bh & 15;
    const int bk = b ^ kvxor;
    const int n0 = blockIdx.x * 128;
    const int qt0 = (b * N_ + n0) >> 4;

    auto cpQ = [&]() {
        #pragma unroll
        for (int q = 0; q < 4; q++) {
            int slot = q * 256 + tid;
            int tile = slot >> 7, j = slot & 127;
            CP_ASYNC16(sb + FQ_OFF + (uint32_t)slot * 16,
                       qf + ((size_t)(qt0 + tile) * 16 + h) * 512 + (size_t)j * 4);
        }
    };
    auto cpK = [&](int st, int ch) {
        int nt0 = (bk * N_ + ch * 128) >> 3;
        #pragma unroll
        for (int q = 0; q < 4; q++) {
            int slot = q * 256 + tid;
            int ntl = slot >> 6, j = slot & 63;
            CP_ASYNC16(sb + FSTG(st) + (uint32_t)slot * 16,
                       kf + ((size_t)(nt0 + ntl) * 16 + h) * 256 + (size_t)j * 4);
        }
    };
    auto cpV = [&](int st, int ch) {
        int vt0 = (bk * N_ + ch * 128) >> 4;
        #pragma unroll
        for (int q = 0; q < 4; q++) {
            int slot = q * 256 + tid;
            int dnt = slot >> 7, rem = slot & 127;
            int skt = rem >> 4, w16 = rem & 15;
            CP_ASYNC16(sb + FSTG(st) + 16384u + (uint32_t)slot * 16,
                       vf + ((size_t)(vt0 + skt) * 16 + h) * 512 + dnt * 64 + (size_t)w16 * 4);
        }
    };

    cpQ(); cpK(0, 0); cpV(0, 0); CP_COMMIT();
    cpK(1, 1); cpV(1, 1); CP_COMMIT();

    uint32_t qh[4][4];
    float o[8][4] = {};
    float m0 = -1e30f, m1 = -1e30f, l0 = 0.f, l1 = 0.f;

    int st = 0;
    for (int ch = 0; ch < 4; ch++) {
        if (ch + 1 < 4) { CP_WAIT1(); } else { CP_WAIT0(); }
        __syncthreads();
        if (ch == 0) {
            #pragma unroll
            for (int kt = 0; kt < 4; kt++) {
                uint4 v = *(const uint4*)(smf + FQ_OFF + (size_t)(((warp * 4 + kt) * 32 + lane) * 4) * 4);
                qh[kt][0] = v.x; qh[kt][1] = v.y; qh[kt][2] = v.z; qh[kt][3] = v.w;
            }
        }
        if (ch + 2 < 4) {
            int ns = st + 2; if (ns >= 3) ns -= 3;
            cpK(ns, ch + 2); cpV(ns, ch + 2); CP_COMMIT();
        }
        const char* kb = smf + FSTG(st);
        const char* vb = smf + FSTG(st) + 16384;

        float s[16][4];
        #pragma unroll
        for (int nt = 0; nt < 16; nt++) { s[nt][0] = s[nt][1] = s[nt][2] = s[nt][3] = 0.f; }
        #pragma unroll
        for (int nt = 0; nt < 16; nt++) {
            #pragma unroll
            for (int kt = 0; kt < 4; kt++) {
                uint32_t kh[2];
                uint2 a = *(const uint2*)(kb + (size_t)(((nt * 4 + kt) * 32 + lane) * 2) * 4);
                kh[0] = a.x; kh[1] = a.y;
                mma_f16(s[nt], qh[kt], kh);
            }
        }

        float cm0 = -1e30f, cm1 = -1e30f;
        #pragma unroll
        for (int nt = 0; nt < 16; nt++) {
            cm0 = fmaxf(cm0, fmaxf(s[nt][0], s[nt][1]));
            cm1 = fmaxf(cm1, fmaxf(s[nt][2], s[nt][3]));
        }
        cm0 = fmaxf(cm0, __shfl_xor_sync(0xffffffffu, cm0, 1));
        cm0 = fmaxf(cm0, __shfl_xor_sync(0xffffffffu, cm0, 2));
        cm1 = fmaxf(cm1, __shfl_xor_sync(0xffffffffu, cm1, 1));
        cm1 = fmaxf(cm1, __shfl_xor_sync(0xffffffffu, cm1, 2));
        float nm0 = fmaxf(m0, cm0), nm1 = fmaxf(m1, cm1);
        float al0 = fast_exp(m0 - nm0), al1 = fast_exp(m1 - nm1);
        m0 = nm0; m1 = nm1;
        #pragma unroll
        for (int dnt = 0; dnt < 8; dnt++) {
            o[dnt][0] *= al0; o[dnt][1] *= al0;
            o[dnt][2] *= al1; o[dnt][3] *= al1;
        }
        float ls0 = 0.f, ls1 = 0.f;

        #pragma unroll
        for (int kt = 0; kt < 8; kt++) {
            float p00 = fast_exp(s[2 * kt][0] - m0);
            float p01 = fast_exp(s[2 * kt][1] - m0);
            float p02 = fast_exp(s[2 * kt][2] - m1);
            float p03 = fast_exp(s[2 * kt][3] - m1);
            float p10 = fast_exp(s[2 * kt + 1][0] - m0);
            float p11 = fast_exp(s[2 * kt + 1][1] - m0);
            float p12 = fast_exp(s[2 * kt + 1][2] - m1);
            float p13 = fast_exp(s[2 * kt + 1][3] - m1);
            ls0 += p00 + p01 + p10 + p11;
            ls1 += p02 + p03 + p12 + p13;
            uint32_t ph[4];
            ph[0] = packh2(p00, p01);
            ph[1] = packh2(p02, p03);
            ph[2] = packh2(p10, p11);
            ph[3] = packh2(p12, p13);
            #pragma unroll
            for (int dnt = 0; dnt < 8; dnt++) {
                uint32_t vh[2];
                uint2 a = *(const uint2*)(vb + (size_t)(((dnt * 8 + kt) * 32 + lane) * 2) * 4);
                vh[0] = a.x; vh[1] = a.y;
                mma_f16(o[dnt], ph, vh);
            }
        }
        ls0 += __shfl_xor_sync(0xffffffffu, ls0, 1);
        ls0 += __shfl_xor_sync(0xffffffffu, ls0, 2);
        ls1 += __shfl_xor_sync(0xffffffffu, ls1, 1);
        ls1 += __shfl_xor_sync(0xffffffffu, ls1, 2);
        l0 = l0 * al0 + ls0;
        l1 = l1 * al1 + ls1;
        if (++st == 3) st = 0;
    }

    __syncthreads();
    uint32_t* sh = (uint32_t*)(smf + FSTG(0));
    float inv0 = 1.0f / l0, inv1 = 1.0f / l1;
    #pragma unroll
    for (int dnt = 0; dnt < 8; dnt++) {
        int kl_ = dnt * 8 + 2 * t;
        int ktl = kl_ >> 4;
        int rk = dnt & 1;
        int baseI = ((warp * 4 + ktl) * 32 + lane) * 4;
        sh[baseI + 2 * rk] = packh2(o[dnt][0] * inv0, o[dnt][1] * inv0);
        sh[baseI + 1 + 2 * rk] = packh2(o[dnt][2] * inv1, o[dnt][3] * inv1);
    }
    __syncthreads();
    #pragma unroll
    for (int q = 0; q < 4; q++) {
        int i = q * 256 + tid;
        int mtl = i >> 7, jj = i & 127;
        size_t gidx = (((size_t)(b * 32 + blockIdx.x * 8 + mtl) * 64) + h * 4) * 128 + (size_t)jj * 4;
        *(uint4*)(Ohi + gidx) = ((const uint4*)sh)[i];
    }
}

// ======================= host orchestration =======================
struct Weights {
    const float *n1g, *n1b, *n2g, *n2b, *pw, *pb, *w1, *b1, *w2, *b2;
};
struct Bufs {
    float *zb;
    uint32_t *qf, *kf, *vf;
    uint32_t *obh, *n2h, *hbh;
    uint32_t *pwh, *w1h, *w2h;
};

static void block_batched(float* resbuf, float* outbuf, int kvxor,
                          const Bufs& B, const Weights& W, const int* guard) {
    lnq_kernel<<<R2_ / 16, 256>>>(resbuf, B.qf, B.kf, B.vf, W.n1g, W.n1b, guard);
    fattn_kernel<<<dim3(4, 8 * NH_), 256, FA_SMEM>>>(B.qf, B.kf, B.vf, kvxor, B.obh, guard);
    gemm_mma<1><<<dim3(C_ / 128, R2_ / 256), 512, GM_SMEM>>>(
        B.obh, B.pwh, outbuf, W.pb, resbuf, nullptr, R2_, C_, C_, guard);
    lnp_kernel<<<R2_ / 16, 256, 32768>>>(outbuf, B.n2h, W.n2g, W.n2b, guard);
    gemm_mma<2><<<dim3(HID_ / 128, R2_ / 256), 512, GM_SMEM>>>(
        B.n2h, B.w1h, nullptr, W.b1, nullptr, B.hbh, R2_, HID_, C_, guard);
    gemm_mma<1><<<dim3(C_ / 128, R2_ / 256), 512, GM_SMEM>>>(
        B.hbh, B.w2h, outbuf, W.b2, outbuf, nullptr, R2_, C_, HID_, guard);
}

extern "C" void kernel_launch(void* const* d_in, const int* in_sizes, int n_in,
                              void* d_out, int out_size) {
    const float* x   = (const float*)d_in[0];
    const float* y   = (const float*)d_in[1];
    Weights W;
    W.n1g = (const float*)d_in[2];  W.n1b = (const float*)d_in[3];
    W.n2g = (const float*)d_in[4];  W.n2b = (const float*)d_in[5];
    W.pw  = (const float*)d_in[6];  W.pb  = (const float*)d_in[7];
    W.w1  = (const float*)d_in[8];  W.b1  = (const float*)d_in[9];
    W.w2  = (const float*)d_in[10]; W.b2  = (const float*)d_in[11];
    const int* flag = (const int*)d_in[12];
    float* out = (float*)d_out;    // 4096 x 1024 = concat(x1, y1)

    Bufs B;
    cudaGetSymbolAddress((void**)&B.zb, g_zb);
    cudaGetSymbolAddress((void**)&B.qf, g_qf);
    cudaGetSymbolAddress((void**)&B.kf, g_kf);
    cudaGetSymbolAddress((void**)&B.vf, g_vf);
    cudaGetSymbolAddress((void**)&B.obh, g_obh);
    cudaGetSymbolAddress((void**)&B.n2h, g_n2h);
    cudaGetSymbolAddress((void**)&B.hbh, g_hbh);
    cudaGetSymbolAddress((void**)&B.pwh, g_pwh);
    cudaGetSymbolAddress((void**)&B.w1h, g_w1h);
    cudaGetSymbolAddress((void**)&B.w2h, g_w2h);

    cudaFuncSetAttribute(gemm_mma<1>, cudaFuncAttributeMaxDynamicSharedMemorySize, GM_SMEM);
    cudaFuncSetAttribute(gemm_mma<2>, cudaFuncAttributeMaxDynamicSharedMemorySize, GM_SMEM);
    cudaFuncSetAttribute(fattn_kernel, cudaFuncAttributeMaxDynamicSharedMemorySize, FA_SMEM);
    cudaFuncSetAttribute(lnp_kernel, cudaFuncAttributeMaxDynamicSharedMemorySize, 32768);

    // weight prep (runs every launch; ~15us)
    pack_weight<<<512, 256>>>(W.pw, B.pwh, C_, C_);
    pack_weight<<<512, 256>>>(W.w1, B.w1h, C_, HID_);
    pack_weight<<<512, 256>>>(W.w2, B.w2h, HID_, C_);

    const size_t bytes = (size_t)R_ * C_ * sizeof(float);
    cudaMemcpyAsync(B.zb, x, bytes, cudaMemcpyDeviceToDevice);
    cudaMemcpyAsync(B.zb + (size_t)R_ * C_, y, bytes, cudaMemcpyDeviceToDevice);

    // x and y self-chains batched as 8 "batches" (x:0-3, y:4-7). Only the
    // FINAL iteration's cross block is live: 4 gated self blocks, then one
    // cross block (kv from opposite half).
    for (int it = 0; it < 4; it++) {
        block_batched(B.zb, B.zb, 0, B, W, flag);
    }
    block_batched(B.zb, out, 4, B, W, nullptr);
}

// round 16
// speedup vs baseline: 1.1427x; 1.1427x over previous
#include <cuda_runtime.h>
#include <cuda_fp16.h>
#include <math.h>
#include <stdint.h>

// Problem dims (fixed by the dataset)
#define B_   4
#define N_   512
#define C_   1024
#define HID_ 4096
#define NH_  16
#define D_   64
#define R_   (B_*N_)     // 2048 rows per stream
#define R2_  (2*R_)      // 4096 rows: x-stream and y-stream batched
#define EPS_ 1e-5f

// ---------------- scratch (device globals: no allocation allowed) ----------
__device__ float g_zb[R2_*C_];    // concat(x, y) residual stream
// fp16 fragment buffers for attention (written by lnq_kernel)
__device__ uint32_t g_qf[R2_*C_/2];     // Q A-frags (scaled 1/8), per (16-row tile, head)
__device__ uint32_t g_kf[R2_*C_/2];     // K B-frags, per (8-row ntile, head)
__device__ uint32_t g_vf[R2_*C_/2];     // V B-frags, per (16-row vtile, head)
// fp16-packed (A-fragment layout) activations
__device__ uint32_t g_obh[R2_*C_/2];    // fattn out -> proj A
__device__ uint32_t g_n2h[R2_*C_/2];    // ln2 out   -> fc1 A
__device__ uint32_t g_hbh[R2_*HID_/2];  // gelu out  -> fc2 A
// fp16 weights packed in mma.m16n8k16 B-fragment layout
__device__ uint32_t g_pwh[C_*C_/2];
__device__ uint32_t g_w1h[C_*HID_/2];
__device__ uint32_t g_w2h[HID_*C_/2];

// ======================= helpers =======================
#define CP_ASYNC16(sm, gp) \
    asm volatile("cp.async.cg.shared.global [%0], [%1], 16;" :: "r"(sm), "l"(gp))
#define CP_COMMIT() asm volatile("cp.async.commit_group;" ::: "memory")
#define CP_WAIT0()  asm volatile("cp.async.wait_group 0;" ::: "memory")
#define CP_WAIT1()  asm volatile("cp.async.wait_group 1;" ::: "memory")

__device__ __forceinline__ uint32_t smem_u32(const void* p) {
    uint32_t a;
    asm("{ .reg .u64 t; cvta.to.shared.u64 t, %1; cvt.u32.u64 %0, t; }" : "=r"(a) : "l"(p));
    return a;
}

__device__ __forceinline__ uint32_t packh2(float a, float b) {
    __half2 h = __halves2half2(__float2half_rn(a), __float2half_rn(b));
    return *(uint32_t*)&h;
}

__device__ __forceinline__ void mma_f16(float* c, const uint32_t* a, const uint32_t* b) {
    asm volatile(
        "mma.sync.aligned.m16n8k16.row.col.f32.f16.f16.f32 "
        "{%0,%1,%2,%3}, {%4,%5,%6,%7}, {%8,%9}, {%0,%1,%2,%3};"
        : "+f"(c[0]), "+f"(c[1]), "+f"(c[2]), "+f"(c[3])
        : "r"(a[0]), "r"(a[1]), "r"(a[2]), "r"(a[3]), "r"(b[0]), "r"(b[1]));
}

__device__ __forceinline__ float fast_exp(float x) {
    float tt = fmaxf(x * 1.4426950408889634f, -126.0f);
    float fi = floorf(tt);
    float f = tt - fi;
    float p = 0.0013333558f;
    p = fmaf(p, f, 0.0096181291f);
    p = fmaf(p, f, 0.0555041087f);
    p = fmaf(p, f, 0.2402265070f);
    p = fmaf(p, f, 0.6931471806f);
    p = fmaf(p, f, 1.0f);
    return p * __int_as_float((__float2int_rn(fi) + 127) << 23);
}

// ===== LN1 -> Q/K/V fp16 fragment buffers (16 rows = 1 q/v tile, 2 k tiles) =
// Low-register variant: rows re-loaded per pass (L1-resident), no payload arrays.
__global__ void __launch_bounds__(256) lnq_kernel(
    const float* __restrict__ in, uint32_t* __restrict__ qf,
    uint32_t* __restrict__ kf, uint32_t* __restrict__ vf,
    const float* __restrict__ gm, const float* __restrict__ bt,
    const int* guard)
{
    if (guard && !guard[0]) return;
    __shared__ uint32_t sh[8192];   // 32KB staging, reused 3x
    const int tid = threadIdx.x;
    const int w = tid >> 5, lane = tid & 31;
    const int row0 = blockIdx.x * 16 + w * 2;
    const float* x0 = in + (size_t)row0 * C_;
    const float* x1 = x0 + C_;

    // ---- pass 0: stats only ----
    float s0 = 0.f, q0 = 0.f, s1 = 0.f, q1 = 0.f;
    #pragma unroll
    for (int i = 0; i < 8; i++) {
        float4 a = *(const float4*)(x0 + i * 128 + lane * 4);
        s0 += a.x + a.y + a.z + a.w;
        q0 += a.x * a.x + a.y * a.y + a.z * a.z + a.w * a.w;
        float4 c = *(const float4*)(x1 + i * 128 + lane * 4);
        s1 += c.x + c.y + c.z + c.w;
        q1 += c.x * c.x + c.y * c.y + c.z * c.z + c.w * c.w;
    }
    #pragma unroll
    for (int o = 16; o; o >>= 1) {
        s0 += __shfl_xor_sync(0xffffffffu, s0, o);
        q0 += __shfl_xor_sync(0xffffffffu, q0, o);
        s1 += __shfl_xor_sync(0xffffffffu, s1, o);
        q1 += __shfl_xor_sync(0xffffffffu, q1, o);
    }
    const float mn0 = s0 * (1.0f / C_);
    const float rs0 = rsqrtf(q0 * (1.0f / C_) - mn0 * mn0 + EPS_);
    const float mn1 = s1 * (1.0f / C_);
    const float rs1 = rsqrtf(q1 * (1.0f / C_) - mn1 * mn1 + EPS_);

    const int ag0 = row0 & 7;
    const int arm = (row0 >> 3) & 1;

    // ---- pass 1: Q A-fragments (scaled 1/8) ----
    #pragma unroll
    for (int i = 0; i < 8; i++) {
        int c = i * 128 + lane * 4;
        float4 va = *(const float4*)(x0 + c);
        float4 vc = *(const float4*)(x1 + c);
        int h = c >> 6, d = c & 63;
        float4 gv = *(const float4*)(gm + c);
        float4 bv = *(const float4*)(bt + c);
        int kt = d >> 4;
        int tt = (d & 7) >> 1;
        int rk = (d & 15) >> 3;
        int bq = h * 512 + (kt * 32 + tt) * 4 + arm + 2 * rk;
        float a0 = ((va.x - mn0) * rs0 * gv.x + bv.x) * 0.125f;
        float a1 = ((va.y - mn0) * rs0 * gv.y + bv.y) * 0.125f;
        float a2 = ((va.z - mn0) * rs0 * gv.z + bv.z) * 0.125f;
        float a3 = ((va.w - mn0) * rs0 * gv.w + bv.w) * 0.125f;
        sh[bq + ag0 * 16] = packh2(a0, a1);
        sh[bq + ag0 * 16 + 4] = packh2(a2, a3);
        float c0 = ((vc.x - mn1) * rs1 * gv.x + bv.x) * 0.125f;
        float c1 = ((vc.y - mn1) * rs1 * gv.y + bv.y) * 0.125f;
        float c2 = ((vc.z - mn1) * rs1 * gv.z + bv.z) * 0.125f;
        float c3 = ((vc.w - mn1) * rs1 * gv.w + bv.w) * 0.125f;
        sh[bq + (ag0 + 1) * 16] = packh2(c0, c1);
        sh[bq + (ag0 + 1) * 16 + 4] = packh2(c2, c3);
    }
    __syncthreads();
    {
        size_t gb = (size_t)blockIdx.x * 8192;
        #pragma unroll
        for (int q = 0; q < 8; q++) {
            int i = q * 256 + tid;
            *(uint4*)(qf + gb + (size_t)i * 4) = ((const uint4*)sh)[i];
        }
    }
    __syncthreads();

    // ---- pass 2: K B-fragments (unscaled) ----
    {
        const int ntl = (row0 >> 3) & 1;
        #pragma unroll
        for (int i = 0; i < 8; i++) {
            int c = i * 128 + lane * 4;
            float4 va = *(const float4*)(x0 + c);
            float4 vc = *(const float4*)(x1 + c);
            int h = c >> 6, d = c & 63;
            float4 gv = *(const float4*)(gm + c);
            float4 bv = *(const float4*)(bt + c);
            int kt = d >> 4;
            int lf = (d & 7) >> 1;
            int reg = (d & 15) >> 3;
            int bk0 = (ntl * 16 + h) * 256 + kt * 64 + reg;
            float a0 = (va.x - mn0) * rs0 * gv.x + bv.x;
            float a1 = (va.y - mn0) * rs0 * gv.y + bv.y;
            float a2 = (va.z - mn0) * rs0 * gv.z + bv.z;
            float a3 = (va.w - mn0) * rs0 * gv.w + bv.w;
            sh[bk0 + (ag0 * 4 + lf) * 2] = packh2(a0, a1);
            sh[bk0 + (ag0 * 4 + lf + 1) * 2] = packh2(a2, a3);
            float c0 = (vc.x - mn1) * rs1 * gv.x + bv.x;
            float c1 = (vc.y - mn1) * rs1 * gv.y + bv.y;
            float c2 = (vc.z - mn1) * rs1 * gv.z + bv.z;
            float c3 = (vc.w - mn1) * rs1 * gv.w + bv.w;
            sh[bk0 + ((ag0 + 1) * 4 + lf) * 2] = packh2(c0, c1);
            sh[bk0 + ((ag0 + 1) * 4 + lf + 1) * 2] = packh2(c2, c3);
        }
    }
    __syncthreads();
    {
        size_t gb = (size_t)blockIdx.x * 8192;
        #pragma unroll
        for (int q = 0; q < 8; q++) {
            int i = q * 256 + tid;
            *(uint4*)(kf + gb + (size_t)i * 4) = ((const uint4*)sh)[i];
        }
    }
    __syncthreads();

    // ---- pass 3: V B-fragments (pairs across rows) ----
    {
        const int reg = (w >> 2) & 1;
        const int lt = w & 3;
        #pragma unroll
        for (int i = 0; i < 8; i++) {
            int c = i * 128 + lane * 4;
            float4 va = *(const float4*)(x0 + c);
            float4 vc = *(const float4*)(x1 + c);
            int h = c >> 6, d0 = c & 63;
            float4 gv = *(const float4*)(gm + c);
            float4 bv = *(const float4*)(bt + c);
            float a[4] = {
                (va.x - mn0) * rs0 * gv.x + bv.x,
                (va.y - mn0) * rs0 * gv.y + bv.y,
                (va.z - mn0) * rs0 * gv.z + bv.z,
                (va.w - mn0) * rs0 * gv.w + bv.w };
            float cc[4] = {
                (vc.x - mn1) * rs1 * gv.x + bv.x,
                (vc.y - mn1) * rs1 * gv.y + bv.y,
                (vc.z - mn1) * rs1 * gv.z + bv.z,
                (vc.w - mn1) * rs1 * gv.w + bv.w };
            #pragma unroll
            for (int e = 0; e < 4; e++) {
                int d = d0 + e;
                int dnt = d >> 3;
                int lanef = (d & 7) * 4 + lt;
                sh[h * 512 + (dnt * 32 + lanef) * 2 + reg] = packh2(a[e], cc[e]);
            }
        }
    }
    __syncthreads();
    {
        size_t gb = (size_t)blockIdx.x * 8192;
        #pragma unroll
        for (int q = 0; q < 8; q++) {
            int i = q * 256 + tid;
            *(uint4*)(vf + gb + (size_t)i * 4) = ((const uint4*)sh)[i];
        }
    }
}

// ============ LayerNorm -> packed fp16 A-fragments (for ln2 -> fc1) =========
__global__ void __launch_bounds__(256) lnp_kernel(
    const float* __restrict__ in, uint32_t* __restrict__ outH,
    const float* __restrict__ gm, const float* __restrict__ bt,
    const int* guard)
{
    if (guard && !guard[0]) return;
    extern __shared__ __align__(16) char sml[];
    uint32_t* sh = (uint32_t*)sml;
    const int w = threadIdx.x >> 5, lane = threadIdx.x & 31;
    #pragma unroll
    for (int rr = 0; rr < 2; rr++) {
        const int row = blockIdx.x * 16 + w * 2 + rr;
        const float* x = in + (size_t)row * C_;
        float s = 0.f, ss = 0.f;
        #pragma unroll
        for (int i = 0; i < 8; i++) {
            float4 v = *(const float4*)(x + i * 128 + lane * 4);
            s += v.x + v.y + v.z + v.w;
            ss += v.x * v.x + v.y * v.y + v.z * v.z + v.w * v.w;
        }
        #pragma unroll
        for (int o = 16; o; o >>= 1) {
            s  += __shfl_xor_sync(0xffffffffu, s, o);
            ss += __shfl_xor_sync(0xffffffffu, ss, o);
        }
        float mean = s * (1.0f / C_);
        float rstd = rsqrtf(ss * (1.0f / C_) - mean * mean + EPS_);
        const int ag = row & 7, m8 = (row >> 3) & 1;
        const int kin = (lane & 3) * 4;
        const int tt0 = (kin & 7) >> 1, rk = kin >> 3;
        #pragma unroll
        for (int i = 0; i < 8; i++) {
            int c = i * 128 + lane * 4;
            float4 v = *(const float4*)(x + c);
            float4 gv = *(const float4*)(gm + c);
            float4 bv = *(const float4*)(bt + c);
            float n0 = (v.x - mean) * rstd * gv.x + bv.x;
            float n1 = (v.y - mean) * rstd * gv.y + bv.y;
            float n2 = (v.z - mean) * rstd * gv.z + bv.z;
            float n3 = (v.w - mean) * rstd * gv.w + bv.w;
            int kt = c >> 4;
            int r = m8 + 2 * rk;
            sh[(kt * 32 + ag * 4 + tt0) * 4 + r] = packh2(n0, n1);
            sh[(kt * 32 + ag * 4 + tt0 + 1) * 4 + r] = packh2(n2, n3);
        }
    }
    __syncthreads();
    size_t gbase = (size_t)blockIdx.x * 8192;
    #pragma unroll
    for (int q = 0; q < 8; q++) {
        int i = q * 256 + threadIdx.x;
        *(uint4*)(outH + gbase + (size_t)i * 4) = ((const uint4*)sh)[i];
    }
}

// ========== weight prep: fp16 pack into B-fragment layout =========
__global__ void pack_weight(const float* __restrict__ W, uint32_t* __restrict__ hiP,
                            int K, int N) {
    int warp = threadIdx.x >> 5, lane = threadIdx.x & 31;
    int g = lane >> 2, t = lane & 3;
    int ktiles = K >> 4;
    int tiles = (N >> 3) * ktiles;
    for (int tile = blockIdx.x * 8 + warp; tile < tiles; tile += gridDim.x * 8) {
        int ntg = tile / ktiles, ksg = tile % ktiles;
        int n = ntg * 8 + g;
        #pragma unroll
        for (int reg = 0; reg < 2; reg++) {
            int k = ksg * 16 + 2 * t + reg * 8;
            float x0 = W[(size_t)k * N + n];
            float x1 = W[(size_t)(k + 1) * N + n];
            hiP[((size_t)tile * 32 + lane) * 2 + reg] = packh2(x0, x1);
        }
    }
}

// ======================= fp16 mma GEMM (R14 config: 128x128, 2 CTAs/SM) =====
#define GM_STAGE 16384
#define GM_SMEM  (3 * GM_STAGE)

template <int EPI>
__global__ void __launch_bounds__(256, 2) gemm_mma(
    const uint32_t* __restrict__ AP, const uint32_t* __restrict__ BP,
    float* __restrict__ Cout, const float* __restrict__ bias,
    const float* __restrict__ res, uint32_t* __restrict__ OutHi,
    int M, int Nt, int K, const int* guard)
{
    if (guard && !guard[0]) return;
    extern __shared__ __align__(16) char smc[];
    const int tid = threadIdx.x;
    const int warp = tid >> 5, lane = tid & 31;
    const int g = lane >> 2, t = lane & 3;
    const int wm = warp & 1, wn = warp >> 1;
    const int bm = blockIdx.y * 128, bn = blockIdx.x * 128;
    const uint32_t sb = smem_u32(smc);

    const int NIT = K >> 5;
    const int ktiles = K >> 4;
    const int bm16 = bm >> 4, bn8 = bn >> 3;

    auto cpA = [&](int stage, int it) {
        uint32_t dstb = sb + stage * GM_STAGE;
        int kt0 = it * 2;
        #pragma unroll
        for (int q = 0; q < 2; q++) {
            int chunk = q * 256 + tid;
            int mtk = chunk >> 5, j = chunk & 31;
            int mtl = mtk >> 1, ktl = mtk & 1;
            size_t gidx = (((size_t)(bm16 + mtl) * ktiles + kt0 + ktl) * 32 + j) * 4;
            CP_ASYNC16(dstb + (uint32_t)(mtk * 512 + j * 16), AP + gidx);
        }
    };
    auto cpB = [&](int stage, int it) {
        uint32_t dstb = sb + stage * GM_STAGE + 8192u;
        int ksg0 = it * 2;
        #pragma unroll
        for (int q = 0; q < 2; q++) {
            int i = q * 256 + tid;
            int nt = i >> 5, j = i & 31;
            size_t srcoff = (((size_t)(bn8 + nt) * ktiles + ksg0) * 64 + (size_t)j * 4);
            CP_ASYNC16(dstb + (uint32_t)(nt * 512 + j * 16), BP + srcoff);
        }
    };

    float acc[4][4][4] = {};

    auto compute = [&](int stage) {
        char* base = smc + stage * GM_STAGE;
        #pragma unroll
        for (int ks = 0; ks < 2; ks++) {
            uint32_t ah[4][4], bh[4][2];
            #pragma unroll
            for (int mt = 0; mt < 4; mt++) {
                uint32_t off = (uint32_t)(((wm * 4 + mt) * 2 + ks) * 32 + lane) * 16;
                uint4 v = *(const uint4*)(base + off);
                ah[mt][0] = v.x; ah[mt][1] = v.y; ah[mt][2] = v.z; ah[mt][3] = v.w;
            }
            #pragma unroll
            for (int nt = 0; nt < 4; nt++) {
                uint32_t off = 8192u + (uint32_t)(((wn * 4 + nt) * 2 + ks) * 32 + lane) * 8;
                uint2 v = *(const uint2*)(base + off);
                bh[nt][0] = v.x; bh[nt][1] = v.y;
            }
            #pragma unroll
            for (int mt = 0; mt < 4; mt++)
                #pragma unroll
                for (int nt = 0; nt < 4; nt++)
                    mma_f16(acc[mt][nt], ah[mt], bh[nt]);
        }
    };

    cpA(0, 0); cpB(0, 0); CP_COMMIT();
    cpA(1, 1); cpB(1, 1); CP_COMMIT();

    int st = 0;
    for (int it = 0; it < NIT; it++) {
        if (it + 1 < NIT) { CP_WAIT1(); } else { CP_WAIT0(); }
        __syncthreads();
        if (it + 2 < NIT) {
            int ns = st + 2; if (ns >= 3) ns -= 3;
            cpA(ns, it + 2); cpB(ns, it + 2); CP_COMMIT();
        }
        compute(st);
        if (++st == 3) st = 0;
    }
    __syncthreads();

    if (EPI == 1) {
        #pragma unroll
        for (int mt = 0; mt < 4; mt++) {
            #pragma unroll
            for (int nt = 0; nt < 4; nt++) {
                int row0 = bm + wm * 64 + mt * 16 + g;
                int col = bn + wn * 32 + nt * 8 + t * 2;
                float2 bv = *(const float2*)&bias[col];
                float v0 = acc[mt][nt][0] + bv.x;
                float v1 = acc[mt][nt][1] + bv.y;
                float v2 = acc[mt][nt][2] + bv.x;
                float v3 = acc[mt][nt][3] + bv.y;
                size_t i0 = (size_t)row0 * Nt + col;
                size_t i1 = (size_t)(row0 + 8) * Nt + col;
                float2 r0 = *(const float2*)&res[i0];
                float2 r1 = *(const float2*)&res[i1];
                *(float2*)&Cout[i0] = make_float2(v0 + r0.x, v1 + r0.y);
                *(float2*)&Cout[i1] = make_float2(v2 + r1.x, v3 + r1.y);
            }
        }
    } else {
        uint32_t* sh = (uint32_t*)smc;
        #pragma unroll
        for (int mt = 0; mt < 4; mt++) {
            #pragma unroll
            for (int nt = 0; nt < 4; nt++) {
                int kl = wn * 32 + nt * 8 + t * 2;
                float2 bv = *(const float2*)&bias[bn + kl];
                float v0 = acc[mt][nt][0] + bv.x;
                float v1 = acc[mt][nt][1] + bv.y;
                float v2 = acc[mt][nt][2] + bv.x;
                float v3 = acc[mt][nt][3] + bv.y;
                v0 = 0.5f * v0 * (1.0f + erff(v0 * 0.70710678118654752f));
                v1 = 0.5f * v1 * (1.0f + erff(v1 * 0.70710678118654752f));
                v2 = 0.5f * v2 * (1.0f + erff(v2 * 0.70710678118654752f));
                v3 = 0.5f * v3 * (1.0f + erff(v3 * 0.70710678118654752f));
                int mtl = wm * 4 + mt;
                int ktl = kl >> 4;
                int tt = (kl & 7) >> 1;
                int rk = (kl >> 3) & 1;
                int baseI = ((mtl * 8 + ktl) * 32 + g * 4 + tt) * 4;
                sh[baseI + 2 * rk] = packh2(v0, v1);
                sh[baseI + 1 + 2 * rk] = packh2(v2, v3);
            }
        }
        __syncthreads();
        const int ktO = Nt >> 4;
        #pragma unroll
        for (int q = 0; q < 8; q++) {
            int i = q * 256 + tid;
            int mtl = i >> 8, jj = i & 255;
            size_t gidx = (((size_t)(bm16 + mtl) * ktO + (bn >> 4)) * 128) + (size_t)jj * 4;
            *(uint4*)(OutHi + gidx) = ((const uint4*)sh)[i];
        }
    }
}

// ============ flash attention: pure cp.async fragments + fp16 mma ===========
#define FQ_OFF  0
#define FSTG(st) (16384 + (st) * 32768)
#define FA_SMEM (16384 + 3 * 32768)   // 112KB

__global__ void __launch_bounds__(256, 1) fattn_kernel(
    const uint32_t* __restrict__ qf, const uint32_t* __restrict__ kf,
    const uint32_t* __restrict__ vf, int kvxor,
    uint32_t* __restrict__ Ohi, const int* guard)
{
    if (guard && !guard[0]) return;
    extern __shared__ __align__(16) char smf[];
    const uint32_t sb = smem_u32(smf);
    const int tid = threadIdx.x, lane = tid & 31, warp = tid >> 5;
    const int g = lane >> 2, t = lane & 3;
    const int bh = blockIdx.y, b = bh >> 4, h = bh & 15;
    const int bk = b ^ kvxor;
    const int n0 = blockIdx.x * 128;
    const int qt0 = (b * N_ + n0) >> 4;

    auto cpQ = [&]() {
        #pragma unroll
        for (int q = 0; q < 4; q++) {
            int slot = q * 256 + tid;
            int tile = slot >> 7, j = slot & 127;
            CP_ASYNC16(sb + FQ_OFF + (uint32_t)slot * 16,
                       qf + ((size_t)(qt0 + tile) * 16 + h) * 512 + (size_t)j * 4);
        }
    };
    auto cpK = [&](int st, int ch) {
        int nt0 = (bk * N_ + ch * 128) >> 3;
        #pragma unroll
        for (int q = 0; q < 4; q++) {
            int slot = q * 256 + tid;
            int ntl = slot >> 6, j = slot & 63;
            CP_ASYNC16(sb + FSTG(st) + (uint32_t)slot * 16,
                       kf + ((size_t)(nt0 + ntl) * 16 + h) * 256 + (size_t)j * 4);
        }
    };
    auto cpV = [&](int st, int ch) {
        int vt0 = (bk * N_ + ch * 128) >> 4;
        #pragma unroll
        for (int q = 0; q < 4; q++) {
            int slot = q * 256 + tid;
            int dnt = slot >> 7, rem = slot & 127;
            int skt = rem >> 4, w16 = rem & 15;
            CP_ASYNC16(sb + FSTG(st) + 16384u + (uint32_t)slot * 16,
                       vf + ((size_t)(vt0 + skt) * 16 + h) * 512 + dnt * 64 + (size_t)w16 * 4);
        }
    };

    cpQ(); cpK(0, 0); cpV(0, 0); CP_COMMIT();
    cpK(1, 1); cpV(1, 1); CP_COMMIT();

    uint32_t qh[4][4];
    float o[8][4] = {};
    float m0 = -1e30f, m1 = -1e30f, l0 = 0.f, l1 = 0.f;

    int st = 0;
    for (int ch = 0; ch < 4; ch++) {
        if (ch + 1 < 4) { CP_WAIT1(); } else { CP_WAIT0(); }
        __syncthreads();
        if (ch == 0) {
            #pragma unroll
            for (int kt = 0; kt < 4; kt++) {
                uint4 v = *(const uint4*)(smf + FQ_OFF + (size_t)(((warp * 4 + kt) * 32 + lane) * 4) * 4);
                qh[kt][0] = v.x; qh[kt][1] = v.y; qh[kt][2] = v.z; qh[kt][3] = v.w;
            }
        }
        if (ch + 2 < 4) {
            int ns = st + 2; if (ns >= 3) ns -= 3;
            cpK(ns, ch + 2); cpV(ns, ch + 2); CP_COMMIT();
        }
        const char* kb = smf + FSTG(st);
        const char* vb = smf + FSTG(st) + 16384;

        float s[16][4];
        #pragma unroll
        for (int nt = 0; nt < 16; nt++) { s[nt][0] = s[nt][1] = s[nt][2] = s[nt][3] = 0.f; }
        #pragma unroll
        for (int nt = 0; nt < 16; nt++) {
            #pragma unroll
            for (int kt = 0; kt < 4; kt++) {
                uint32_t kh[2];
                uint2 a = *(const uint2*)(kb + (size_t)(((nt * 4 + kt) * 32 + lane) * 2) * 4);
                kh[0] = a.x; kh[1] = a.y;
                mma_f16(s[nt], qh[kt], kh);
            }
        }

        float cm0 = -1e30f, cm1 = -1e30f;
        #pragma unroll
        for (int nt = 0; nt < 16; nt++) {
            cm0 = fmaxf(cm0, fmaxf(s[nt][0], s[nt][1]));
            cm1 = fmaxf(cm1, fmaxf(s[nt][2], s[nt][3]));
        }
        cm0 = fmaxf(cm0, __shfl_xor_sync(0xffffffffu, cm0, 1));
        cm0 = fmaxf(cm0, __shfl_xor_sync(0xffffffffu, cm0, 2));
        cm1 = fmaxf(cm1, __shfl_xor_sync(0xffffffffu, cm1, 1));
        cm1 = fmaxf(cm1, __shfl_xor_sync(0xffffffffu, cm1, 2));
        float nm0 = fmaxf(m0, cm0), nm1 = fmaxf(m1, cm1);
        float al0 = fast_exp(m0 - nm0), al1 = fast_exp(m1 - nm1);
        m0 = nm0; m1 = nm1;
        #pragma unroll
        for (int dnt = 0; dnt < 8; dnt++) {
            o[dnt][0] *= al0; o[dnt][1] *= al0;
            o[dnt][2] *= al1; o[dnt][3] *= al1;
        }
        float ls0 = 0.f, ls1 = 0.f;

        #pragma unroll
        for (int kt = 0; kt < 8; kt++) {
            float p00 = fast_exp(s[2 * kt][0] - m0);
            float p01 = fast_exp(s[2 * kt][1] - m0);
            float p02 = fast_exp(s[2 * kt][2] - m1);
            float p03 = fast_exp(s[2 * kt][3] - m1);
            float p10 = fast_exp(s[2 * kt + 1][0] - m0);
            float p11 = fast_exp(s[2 * kt + 1][1] - m0);
            float p12 = fast_exp(s[2 * kt + 1][2] - m1);
            float p13 = fast_exp(s[2 * kt + 1][3] - m1);
            ls0 += p00 + p01 + p10 + p11;
            ls1 += p02 + p03 + p12 + p13;
            uint32_t ph[4];
            ph[0] = packh2(p00, p01);
            ph[1] = packh2(p02, p03);
            ph[2] = packh2(p10, p11);
            ph[3] = packh2(p12, p13);
            #pragma unroll
            for (int dnt = 0; dnt < 8; dnt++) {
                uint32_t vh[2];
                uint2 a = *(const uint2*)(vb + (size_t)(((dnt * 8 + kt) * 32 + lane) * 2) * 4);
                vh[0] = a.x; vh[1] = a.y;
                mma_f16(o[dnt], ph, vh);
            }
        }
        ls0 += __shfl_xor_sync(0xffffffffu, ls0, 1);
        ls0 += __shfl_xor_sync(0xffffffffu, ls0, 2);
        ls1 += __shfl_xor_sync(0xffffffffu, ls1, 1);
        ls1 += __shfl_xor_sync(0xffffffffu, ls1, 2);
        l0 = l0 * al0 + ls0;
        l1 = l1 * al1 + ls1;
        if (++st == 3) st = 0;
    }

    __syncthreads();
    uint32_t* sh = (uint32_t*)(smf + FSTG(0));
    float inv0 = 1.0f / l0, inv1 = 1.0f / l1;
    #pragma unroll
    for (int dnt = 0; dnt < 8; dnt++) {
        int kl_ = dnt * 8 + 2 * t;
        int ktl = kl_ >> 4;
        int rk = dnt & 1;
        int baseI = ((warp * 4 + ktl) * 32 + lane) * 4;
        sh[baseI + 2 * rk] = packh2(o[dnt][0] * inv0, o[dnt][1] * inv0);
        sh[baseI + 1 + 2 * rk] = packh2(o[dnt][2] * inv1, o[dnt][3] * inv1);
    }
    __syncthreads();
    #pragma unroll
    for (int q = 0; q < 4; q++) {
        int i = q * 256 + tid;
        int mtl = i >> 7, jj = i & 127;
        size_t gidx = (((size_t)(b * 32 + blockIdx.x * 8 + mtl) * 64) + h * 4) * 128 + (size_t)jj * 4;
        *(uint4*)(Ohi + gidx) = ((const uint4*)sh)[i];
    }
}

// ======================= host orchestration =======================
struct Weights {
    const float *n1g, *n1b, *n2g, *n2b, *pw, *pb, *w1, *b1, *w2, *b2;
};
struct Bufs {
    float *zb;
    uint32_t *qf, *kf, *vf;
    uint32_t *obh, *n2h, *hbh;
    uint32_t *pwh, *w1h, *w2h;
};

static void block_batched(float* resbuf, float* outbuf, int kvxor,
                          const Bufs& B, const Weights& W, const int* guard) {
    lnq_kernel<<<R2_ / 16, 256>>>(resbuf, B.qf, B.kf, B.vf, W.n1g, W.n1b, guard);
    fattn_kernel<<<dim3(4, 8 * NH_), 256, FA_SMEM>>>(B.qf, B.kf, B.vf, kvxor, B.obh, guard);
    gemm_mma<1><<<dim3(C_ / 128, R2_ / 128), 256, GM_SMEM>>>(
        B.obh, B.pwh, outbuf, W.pb, resbuf, nullptr, R2_, C_, C_, guard);
    lnp_kernel<<<R2_ / 16, 256, 32768>>>(outbuf, B.n2h, W.n2g, W.n2b, guard);
    gemm_mma<2><<<dim3(HID_ / 128, R2_ / 128), 256, GM_SMEM>>>(
        B.n2h, B.w1h, nullptr, W.b1, nullptr, B.hbh, R2_, HID_, C_, guard);
    gemm_mma<1><<<dim3(C_ / 128, R2_ / 128), 256, GM_SMEM>>>(
        B.hbh, B.w2h, outbuf, W.b2, outbuf, nullptr, R2_, C_, HID_, guard);
}

extern "C" void kernel_launch(void* const* d_in, const int* in_sizes, int n_in,
                              void* d_out, int out_size) {
    const float* x   = (const float*)d_in[0];
    const float* y   = (const float*)d_in[1];
    Weights W;
    W.n1g = (const float*)d_in[2];  W.n1b = (const float*)d_in[3];
    W.n2g = (const float*)d_in[4];  W.n2b = (const float*)d_in[5];
    W.pw  = (const float*)d_in[6];  W.pb  = (const float*)d_in[7];
    W.w1  = (const float*)d_in[8];  W.b1  = (const float*)d_in[9];
    W.w2  = (const float*)d_in[10]; W.b2  = (const float*)d_in[11];
    const int* flag = (const int*)d_in[12];
    float* out = (float*)d_out;    // 4096 x 1024 = concat(x1, y1)

    Bufs B;
    cudaGetSymbolAddress((void**)&B.zb, g_zb);
    cudaGetSymbolAddress((void**)&B.qf, g_qf);
    cudaGetSymbolAddress((void**)&B.kf, g_kf);
    cudaGetSymbolAddress((void**)&B.vf, g_vf);
    cudaGetSymbolAddress((void**)&B.obh, g_obh);
    cudaGetSymbolAddress((void**)&B.n2h, g_n2h);
    cudaGetSymbolAddress((void**)&B.hbh, g_hbh);
    cudaGetSymbolAddress((void**)&B.pwh, g_pwh);
    cudaGetSymbolAddress((void**)&B.w1h, g_w1h);
    cudaGetSymbolAddress((void**)&B.w2h, g_w2h);

    cudaFuncSetAttribute(gemm_mma<1>, cudaFuncAttributeMaxDynamicSharedMemorySize, GM_SMEM);
    cudaFuncSetAttribute(gemm_mma<2>, cudaFuncAttributeMaxDynamicSharedMemorySize, GM_SMEM);
    cudaFuncSetAttribute(fattn_kernel, cudaFuncAttributeMaxDynamicSharedMemorySize, FA_SMEM);
    cudaFuncSetAttribute(lnp_kernel, cudaFuncAttributeMaxDynamicSharedMemorySize, 32768);

    // weight prep (runs every launch; ~15us)
    pack_weight<<<512, 256>>>(W.pw, B.pwh, C_, C_);
    pack_weight<<<512, 256>>>(W.w1, B.w1h, C_, HID_);
    pack_weight<<<512, 256>>>(W.w2, B.w2h, HID_, C_);

    const size_t bytes = (size_t)R_ * C_ * sizeof(float);
    cudaMemcpyAsync(B.zb, x, bytes, cudaMemcpyDeviceToDevice);
    cudaMemcpyAsync(B.zb + (size_t)R_ * C_, y, bytes, cudaMemcpyDeviceToDevice);

    // x and y self-chains batched as 8 "batches" (x:0-3, y:4-7). Only the
    // FINAL iteration's cross block is live: 4 gated self blocks, then one
    // cross block (kv from opposite half).
    for (int it = 0; it < 4; it++) {
        block_batched(B.zb, B.zb, 0, B, W, flag);
    }
    block_batched(B.zb, out, 4, B, W, nullptr);
}

// round 17
// speedup vs baseline: 1.1490x; 1.0055x over previous
#include <cuda_runtime.h>
#include <cuda_fp16.h>
#include <math.h>
#include <stdint.h>

// Problem dims (fixed by the dataset)
#define B_   4
#define N_   512
#define C_   1024
#define HID_ 4096
#define NH_  16
#define D_   64
#define R_   (B_*N_)     // 2048 rows per stream
#define R2_  (2*R_)      // 4096 rows: x-stream and y-stream batched
#define EPS_ 1e-5f

// ---------------- scratch (device globals: no allocation allowed) ----------
__device__ float g_zb[R2_*C_];    // concat(x, y) residual stream
// fp16 fragment buffers for attention (written by lnq_kernel)
__device__ uint32_t g_qf[R2_*C_/2];     // Q A-frags (scaled 1/8), per (16-row tile, head)
__device__ uint32_t g_kf[R2_*C_/2];     // K B-frags, per (8-row ntile, head)
__device__ uint32_t g_vf[R2_*C_/2];     // V B-frags, per (16-row vtile, head)
// fp16-packed (A-fragment layout) activations
__device__ uint32_t g_obh[R2_*C_/2];    // fattn out -> proj A
__device__ uint32_t g_n2h[R2_*C_/2];    // ln2 out   -> fc1 A
__device__ uint32_t g_hbh[R2_*HID_/2];  // gelu out  -> fc2 A
// fp16 weights packed in mma.m16n8k16 B-fragment layout
__device__ uint32_t g_pwh[C_*C_/2];
__device__ uint32_t g_w1h[C_*HID_/2];
__device__ uint32_t g_w2h[HID_*C_/2];

// ======================= helpers =======================
#define CP_ASYNC16(sm, gp) \
    asm volatile("cp.async.cg.shared.global [%0], [%1], 16;" :: "r"(sm), "l"(gp))
#define CP_COMMIT() asm volatile("cp.async.commit_group;" ::: "memory")
#define CP_WAIT0()  asm volatile("cp.async.wait_group 0;" ::: "memory")
#define CP_WAIT1()  asm volatile("cp.async.wait_group 1;" ::: "memory")

__device__ __forceinline__ uint32_t smem_u32(const void* p) {
    uint32_t a;
    asm("{ .reg .u64 t; cvta.to.shared.u64 t, %1; cvt.u32.u64 %0, t; }" : "=r"(a) : "l"(p));
    return a;
}

__device__ __forceinline__ uint32_t packh2(float a, float b) {
    __half2 h = __halves2half2(__float2half_rn(a), __float2half_rn(b));
    return *(uint32_t*)&h;
}

__device__ __forceinline__ void mma_f16(float* c, const uint32_t* a, const uint32_t* b) {
    asm volatile(
        "mma.sync.aligned.m16n8k16.row.col.f32.f16.f16.f32 "
        "{%0,%1,%2,%3}, {%4,%5,%6,%7}, {%8,%9}, {%0,%1,%2,%3};"
        : "+f"(c[0]), "+f"(c[1]), "+f"(c[2]), "+f"(c[3])
        : "r"(a[0]), "r"(a[1]), "r"(a[2]), "r"(a[3]), "r"(b[0]), "r"(b[1]));
}

__device__ __forceinline__ float fast_exp(float x) {
    float tt = fmaxf(x * 1.4426950408889634f, -126.0f);
    float fi = floorf(tt);
    float f = tt - fi;
    float p = 0.0013333558f;
    p = fmaf(p, f, 0.0096181291f);
    p = fmaf(p, f, 0.0555041087f);
    p = fmaf(p, f, 0.2402265070f);
    p = fmaf(p, f, 0.6931471806f);
    p = fmaf(p, f, 1.0f);
    return p * __int_as_float((__float2int_rn(fi) + 127) << 23);
}

// ===== LN1 -> Q/K/V fp16 fragment buffers; forced 3 CTAs/SM ================
__global__ void __launch_bounds__(256, 3) lnq_kernel(
    const float* __restrict__ in, uint32_t* __restrict__ qf,
    uint32_t* __restrict__ kf, uint32_t* __restrict__ vf,
    const float* __restrict__ gm, const float* __restrict__ bt,
    const int* guard)
{
    if (guard && !guard[0]) return;
    __shared__ uint32_t sh[8192];   // 32KB staging, reused 3x
    const int tid = threadIdx.x;
    const int w = tid >> 5, lane = tid & 31;
    const int row0 = blockIdx.x * 16 + w * 2;
    const float* x0 = in + (size_t)row0 * C_;
    const float* x1 = x0 + C_;

    // ---- pass 0: stats only ----
    float s0 = 0.f, q0 = 0.f, s1 = 0.f, q1 = 0.f;
    #pragma unroll
    for (int i = 0; i < 8; i++) {
        float4 a = *(const float4*)(x0 + i * 128 + lane * 4);
        s0 += a.x + a.y + a.z + a.w;
        q0 += a.x * a.x + a.y * a.y + a.z * a.z + a.w * a.w;
        float4 c = *(const float4*)(x1 + i * 128 + lane * 4);
        s1 += c.x + c.y + c.z + c.w;
        q1 += c.x * c.x + c.y * c.y + c.z * c.z + c.w * c.w;
    }
    #pragma unroll
    for (int o = 16; o; o >>= 1) {
        s0 += __shfl_xor_sync(0xffffffffu, s0, o);
        q0 += __shfl_xor_sync(0xffffffffu, q0, o);
        s1 += __shfl_xor_sync(0xffffffffu, s1, o);
        q1 += __shfl_xor_sync(0xffffffffu, q1, o);
    }
    const float mn0 = s0 * (1.0f / C_);
    const float rs0 = rsqrtf(q0 * (1.0f / C_) - mn0 * mn0 + EPS_);
    const float mn1 = s1 * (1.0f / C_);
    const float rs1 = rsqrtf(q1 * (1.0f / C_) - mn1 * mn1 + EPS_);

    const int ag0 = row0 & 7;
    const int arm = (row0 >> 3) & 1;

    // ---- pass 1: Q A-fragments (scaled 1/8) ----
    #pragma unroll
    for (int i = 0; i < 8; i++) {
        int c = i * 128 + lane * 4;
        float4 va = *(const float4*)(x0 + c);
        float4 vc = *(const float4*)(x1 + c);
        int h = c >> 6, d = c & 63;
        float4 gv = *(const float4*)(gm + c);
        float4 bv = *(const float4*)(bt + c);
        int kt = d >> 4;
        int tt = (d & 7) >> 1;
        int rk = (d & 15) >> 3;
        int bq = h * 512 + (kt * 32 + tt) * 4 + arm + 2 * rk;
        float a0 = ((va.x - mn0) * rs0 * gv.x + bv.x) * 0.125f;
        float a1 = ((va.y - mn0) * rs0 * gv.y + bv.y) * 0.125f;
        float a2 = ((va.z - mn0) * rs0 * gv.z + bv.z) * 0.125f;
        float a3 = ((va.w - mn0) * rs0 * gv.w + bv.w) * 0.125f;
        sh[bq + ag0 * 16] = packh2(a0, a1);
        sh[bq + ag0 * 16 + 4] = packh2(a2, a3);
        float c0 = ((vc.x - mn1) * rs1 * gv.x + bv.x) * 0.125f;
        float c1 = ((vc.y - mn1) * rs1 * gv.y + bv.y) * 0.125f;
        float c2 = ((vc.z - mn1) * rs1 * gv.z + bv.z) * 0.125f;
        float c3 = ((vc.w - mn1) * rs1 * gv.w + bv.w) * 0.125f;
        sh[bq + (ag0 + 1) * 16] = packh2(c0, c1);
        sh[bq + (ag0 + 1) * 16 + 4] = packh2(c2, c3);
    }
    __syncthreads();
    {
        size_t gb = (size_t)blockIdx.x * 8192;
        #pragma unroll
        for (int q = 0; q < 8; q++) {
            int i = q * 256 + tid;
            *(uint4*)(qf + gb + (size_t)i * 4) = ((const uint4*)sh)[i];
        }
    }
    __syncthreads();

    // ---- pass 2: K B-fragments (unscaled) ----
    {
        const int ntl = (row0 >> 3) & 1;
        #pragma unroll
        for (int i = 0; i < 8; i++) {
            int c = i * 128 + lane * 4;
            float4 va = *(const float4*)(x0 + c);
            float4 vc = *(const float4*)(x1 + c);
            int h = c >> 6, d = c & 63;
            float4 gv = *(const float4*)(gm + c);
            float4 bv = *(const float4*)(bt + c);
            int kt = d >> 4;
            int lf = (d & 7) >> 1;
            int reg = (d & 15) >> 3;
            int bk0 = (ntl * 16 + h) * 256 + kt * 64 + reg;
            float a0 = (va.x - mn0) * rs0 * gv.x + bv.x;
            float a1 = (va.y - mn0) * rs0 * gv.y + bv.y;
            float a2 = (va.z - mn0) * rs0 * gv.z + bv.z;
            float a3 = (va.w - mn0) * rs0 * gv.w + bv.w;
            sh[bk0 + (ag0 * 4 + lf) * 2] = packh2(a0, a1);
            sh[bk0 + (ag0 * 4 + lf + 1) * 2] = packh2(a2, a3);
            float c0 = (vc.x - mn1) * rs1 * gv.x + bv.x;
            float c1 = (vc.y - mn1) * rs1 * gv.y + bv.y;
            float c2 = (vc.z - mn1) * rs1 * gv.z + bv.z;
            float c3 = (vc.w - mn1) * rs1 * gv.w + bv.w;
            sh[bk0 + ((ag0 + 1) * 4 + lf) * 2] = packh2(c0, c1);
            sh[bk0 + ((ag0 + 1) * 4 + lf + 1) * 2] = packh2(c2, c3);
        }
    }
    __syncthreads();
    {
        size_t gb = (size_t)blockIdx.x * 8192;
        #pragma unroll
        for (int q = 0; q < 8; q++) {
            int i = q * 256 + tid;
            *(uint4*)(kf + gb + (size_t)i * 4) = ((const uint4*)sh)[i];
        }
    }
    __syncthreads();

    // ---- pass 3: V B-fragments (pairs across rows) ----
    {
        const int reg = (w >> 2) & 1;
        const int lt = w & 3;
        #pragma unroll
        for (int i = 0; i < 8; i++) {
            int c = i * 128 + lane * 4;
            float4 va = *(const float4*)(x0 + c);
            float4 vc = *(const float4*)(x1 + c);
            int h = c >> 6, d0 = c & 63;
            float4 gv = *(const float4*)(gm + c);
            float4 bv = *(const float4*)(bt + c);
            float a[4] = {
                (va.x - mn0) * rs0 * gv.x + bv.x,
                (va.y - mn0) * rs0 * gv.y + bv.y,
                (va.z - mn0) * rs0 * gv.z + bv.z,
                (va.w - mn0) * rs0 * gv.w + bv.w };
            float cc[4] = {
                (vc.x - mn1) * rs1 * gv.x + bv.x,
                (vc.y - mn1) * rs1 * gv.y + bv.y,
                (vc.z - mn1) * rs1 * gv.z + bv.z,
                (vc.w - mn1) * rs1 * gv.w + bv.w };
            #pragma unroll
            for (int e = 0; e < 4; e++) {
                int d = d0 + e;
                int dnt = d >> 3;
                int lanef = (d & 7) * 4 + lt;
                sh[h * 512 + (dnt * 32 + lanef) * 2 + reg] = packh2(a[e], cc[e]);
            }
        }
    }
    __syncthreads();
    {
        size_t gb = (size_t)blockIdx.x * 8192;
        #pragma unroll
        for (int q = 0; q < 8; q++) {
            int i = q * 256 + tid;
            *(uint4*)(vf + gb + (size_t)i * 4) = ((const uint4*)sh)[i];
        }
    }
}

// ============ LayerNorm -> packed fp16 A-fragments (for ln2 -> fc1) =========
__global__ void __launch_bounds__(256) lnp_kernel(
    const float* __restrict__ in, uint32_t* __restrict__ outH,
    const float* __restrict__ gm, const float* __restrict__ bt,
    const int* guard)
{
    if (guard && !guard[0]) return;
    extern __shared__ __align__(16) char sml[];
    uint32_t* sh = (uint32_t*)sml;
    const int w = threadIdx.x >> 5, lane = threadIdx.x & 31;
    #pragma unroll
    for (int rr = 0; rr < 2; rr++) {
        const int row = blockIdx.x * 16 + w * 2 + rr;
        const float* x = in + (size_t)row * C_;
        float s = 0.f, ss = 0.f;
        #pragma unroll
        for (int i = 0; i < 8; i++) {
            float4 v = *(const float4*)(x + i * 128 + lane * 4);
            s += v.x + v.y + v.z + v.w;
            ss += v.x * v.x + v.y * v.y + v.z * v.z + v.w * v.w;
        }
        #pragma unroll
        for (int o = 16; o; o >>= 1) {
            s  += __shfl_xor_sync(0xffffffffu, s, o);
            ss += __shfl_xor_sync(0xffffffffu, ss, o);
        }
        float mean = s * (1.0f / C_);
        float rstd = rsqrtf(ss * (1.0f / C_) - mean * mean + EPS_);
        const int ag = row & 7, m8 = (row >> 3) & 1;
        const int kin = (lane & 3) * 4;
        const int tt0 = (kin & 7) >> 1, rk = kin >> 3;
        #pragma unroll
        for (int i = 0; i < 8; i++) {
            int c = i * 128 + lane * 4;
            float4 v = *(const float4*)(x + c);
            float4 gv = *(const float4*)(gm + c);
            float4 bv = *(const float4*)(bt + c);
            float n0 = (v.x - mean) * rstd * gv.x + bv.x;
            float n1 = (v.y - mean) * rstd * gv.y + bv.y;
            float n2 = (v.z - mean) * rstd * gv.z + bv.z;
            float n3 = (v.w - mean) * rstd * gv.w + bv.w;
            int kt = c >> 4;
            int r = m8 + 2 * rk;
            sh[(kt * 32 + ag * 4 + tt0) * 4 + r] = packh2(n0, n1);
            sh[(kt * 32 + ag * 4 + tt0 + 1) * 4 + r] = packh2(n2, n3);
        }
    }
    __syncthreads();
    size_t gbase = (size_t)blockIdx.x * 8192;
    #pragma unroll
    for (int q = 0; q < 8; q++) {
        int i = q * 256 + threadIdx.x;
        *(uint4*)(outH + gbase + (size_t)i * 4) = ((const uint4*)sh)[i];
    }
}

// ========== weight prep: fp16 pack into B-fragment layout =========
__global__ void pack_weight(const float* __restrict__ W, uint32_t* __restrict__ hiP,
                            int K, int N) {
    int warp = threadIdx.x >> 5, lane = threadIdx.x & 31;
    int g = lane >> 2, t = lane & 3;
    int ktiles = K >> 4;
    int tiles = (N >> 3) * ktiles;
    for (int tile = blockIdx.x * 8 + warp; tile < tiles; tile += gridDim.x * 8) {
        int ntg = tile / ktiles, ksg = tile % ktiles;
        int n = ntg * 8 + g;
        #pragma unroll
        for (int reg = 0; reg < 2; reg++) {
            int k = ksg * 16 + 2 * t + reg * 8;
            float x0 = W[(size_t)k * N + n];
            float x1 = W[(size_t)(k + 1) * N + n];
            hiP[((size_t)tile * 32 + lane) * 2 + reg] = packh2(x0, x1);
        }
    }
}

// ======================= fp16 mma GEMM (R14 config: 128x128, 2 CTAs/SM) =====
#define GM_STAGE 16384
#define GM_SMEM  (3 * GM_STAGE)

template <int EPI>
__global__ void __launch_bounds__(256, 2) gemm_mma(
    const uint32_t* __restrict__ AP, const uint32_t* __restrict__ BP,
    float* __restrict__ Cout, const float* __restrict__ bias,
    const float* __restrict__ res, uint32_t* __restrict__ OutHi,
    int M, int Nt, int K, const int* guard)
{
    if (guard && !guard[0]) return;
    extern __shared__ __align__(16) char smc[];
    const int tid = threadIdx.x;
    const int warp = tid >> 5, lane = tid & 31;
    const int g = lane >> 2, t = lane & 3;
    const int wm = warp & 1, wn = warp >> 1;
    const int bm = blockIdx.y * 128, bn = blockIdx.x * 128;
    const uint32_t sb = smem_u32(smc);

    const int NIT = K >> 5;
    const int ktiles = K >> 4;
    const int bm16 = bm >> 4, bn8 = bn >> 3;

    auto cpA = [&](int stage, int it) {
        uint32_t dstb = sb + stage * GM_STAGE;
        int kt0 = it * 2;
        #pragma unroll
        for (int q = 0; q < 2; q++) {
            int chunk = q * 256 + tid;
            int mtk = chunk >> 5, j = chunk & 31;
            int mtl = mtk >> 1, ktl = mtk & 1;
            size_t gidx = (((size_t)(bm16 + mtl) * ktiles + kt0 + ktl) * 32 + j) * 4;
            CP_ASYNC16(dstb + (uint32_t)(mtk * 512 + j * 16), AP + gidx);
        }
    };
    auto cpB = [&](int stage, int it) {
        uint32_t dstb = sb + stage * GM_STAGE + 8192u;
        int ksg0 = it * 2;
        #pragma unroll
        for (int q = 0; q < 2; q++) {
            int i = q * 256 + tid;
            int nt = i >> 5, j = i & 31;
            size_t srcoff = (((size_t)(bn8 + nt) * ktiles + ksg0) * 64 + (size_t)j * 4);
            CP_ASYNC16(dstb + (uint32_t)(nt * 512 + j * 16), BP + srcoff);
        }
    };

    float acc[4][4][4] = {};

    auto compute = [&](int stage) {
        char* base = smc + stage * GM_STAGE;
        #pragma unroll
        for (int ks = 0; ks < 2; ks++) {
            uint32_t ah[4][4], bh[4][2];
            #pragma unroll
            for (int mt = 0; mt < 4; mt++) {
                uint32_t off = (uint32_t)(((wm * 4 + mt) * 2 + ks) * 32 + lane) * 16;
                uint4 v = *(const uint4*)(base + off);
                ah[mt][0] = v.x; ah[mt][1] = v.y; ah[mt][2] = v.z; ah[mt][3] = v.w;
            }
            #pragma unroll
            for (int nt = 0; nt < 4; nt++) {
                uint32_t off = 8192u + (uint32_t)(((wn * 4 + nt) * 2 + ks) * 32 + lane) * 8;
                uint2 v = *(const uint2*)(base + off);
                bh[nt][0] = v.x; bh[nt][1] = v.y;
            }
            #pragma unroll
            for (int mt = 0; mt < 4; mt++)
                #pragma unroll
                for (int nt = 0; nt < 4; nt++)
                    mma_f16(acc[mt][nt], ah[mt], bh[nt]);
        }
    };

    cpA(0, 0); cpB(0, 0); CP_COMMIT();
    cpA(1, 1); cpB(1, 1); CP_COMMIT();

    int st = 0;
    for (int it = 0; it < NIT; it++) {
        if (it + 1 < NIT) { CP_WAIT1(); } else { CP_WAIT0(); }
        __syncthreads();
        if (it + 2 < NIT) {
            int ns = st + 2; if (ns >= 3) ns -= 3;
            cpA(ns, it + 2); cpB(ns, it + 2); CP_COMMIT();
        }
        compute(st);
        if (++st == 3) st = 0;
    }
    __syncthreads();

    if (EPI == 1) {
        #pragma unroll
        for (int mt = 0; mt < 4; mt++) {
            #pragma unroll
            for (int nt = 0; nt < 4; nt++) {
                int row0 = bm + wm * 64 + mt * 16 + g;
                int col = bn + wn * 32 + nt * 8 + t * 2;
                float2 bv = *(const float2*)&bias[col];
                float v0 = acc[mt][nt][0] + bv.x;
                float v1 = acc[mt][nt][1] + bv.y;
                float v2 = acc[mt][nt][2] + bv.x;
                float v3 = acc[mt][nt][3] + bv.y;
                size_t i0 = (size_t)row0 * Nt + col;
                size_t i1 = (size_t)(row0 + 8) * Nt + col;
                float2 r0 = *(const float2*)&res[i0];
                float2 r1 = *(const float2*)&res[i1];
                *(float2*)&Cout[i0] = make_float2(v0 + r0.x, v1 + r0.y);
                *(float2*)&Cout[i1] = make_float2(v2 + r1.x, v3 + r1.y);
            }
        }
    } else {
        uint32_t* sh = (uint32_t*)smc;
        #pragma unroll
        for (int mt = 0; mt < 4; mt++) {
            #pragma unroll
            for (int nt = 0; nt < 4; nt++) {
                int kl = wn * 32 + nt * 8 + t * 2;
                float2 bv = *(const float2*)&bias[bn + kl];
                float v0 = acc[mt][nt][0] + bv.x;
                float v1 = acc[mt][nt][1] + bv.y;
                float v2 = acc[mt][nt][2] + bv.x;
                float v3 = acc[mt][nt][3] + bv.y;
                v0 = 0.5f * v0 * (1.0f + erff(v0 * 0.70710678118654752f));
                v1 = 0.5f * v1 * (1.0f + erff(v1 * 0.70710678118654752f));
                v2 = 0.5f * v2 * (1.0f + erff(v2 * 0.70710678118654752f));
                v3 = 0.5f * v3 * (1.0f + erff(v3 * 0.70710678118654752f));
                int mtl = wm * 4 + mt;
                int ktl = kl >> 4;
                int tt = (kl & 7) >> 1;
                int rk = (kl >> 3) & 1;
                int baseI = ((mtl * 8 + ktl) * 32 + g * 4 + tt) * 4;
                sh[baseI + 2 * rk] = packh2(v0, v1);
                sh[baseI + 1 + 2 * rk] = packh2(v2, v3);
            }
        }
        __syncthreads();
        const int ktO = Nt >> 4;
        #pragma unroll
        for (int q = 0; q < 8; q++) {
            int i = q * 256 + tid;
            int mtl = i >> 8, jj = i & 255;
            size_t gidx = (((size_t)(bm16 + mtl) * ktO + (bn >> 4)) * 128) + (size_t)jj * 4;
            *(uint4*)(OutHi + gidx) = ((const uint4*)sh)[i];
        }
    }
}

// ============ flash attention: 2-stage KV pipeline, 2 CTAs/SM ===============
#define FQ_OFF  0
#define FSTG(st) (16384 + (st) * 32768)
#define FA_SMEM (16384 + 2 * 32768)   // 80KB -> 2 CTAs/SM

__global__ void __launch_bounds__(256, 2) fattn_kernel(
    const uint32_t* __restrict__ qf, const uint32_t* __restrict__ kf,
    const uint32_t* __restrict__ vf, int kvxor,
    uint32_t* __restrict__ Ohi, const int* guard)
{
    if (guard && !guard[0]) return;
    extern __shared__ __align__(16) char smf[];
    const uint32_t sb = smem_u32(smf);
    const int tid = threadIdx.x, lane = tid & 31, warp = tid >> 5;
    const int g = lane >> 2, t = lane & 3;
    const int bh = blockIdx.y, b = bh >> 4, h = bh & 15;
    const int bk = b ^ kvxor;
    const int n0 = blockIdx.x * 128;
    const int qt0 = (b * N_ + n0) >> 4;

    auto cpQ = [&]() {
        #pragma unroll
        for (int q = 0; q < 4; q++) {
            int slot = q * 256 + tid;
            int tile = slot >> 7, j = slot & 127;
            CP_ASYNC16(sb + FQ_OFF + (uint32_t)slot * 16,
                       qf + ((size_t)(qt0 + tile) * 16 + h) * 512 + (size_t)j * 4);
        }
    };
    auto cpK = [&](int st, int ch) {
        int nt0 = (bk * N_ + ch * 128) >> 3;
        #pragma unroll
        for (int q = 0; q < 4; q++) {
            int slot = q * 256 + tid;
            int ntl = slot >> 6, j = slot & 63;
            CP_ASYNC16(sb + FSTG(st) + (uint32_t)slot * 16,
                       kf + ((size_t)(nt0 + ntl) * 16 + h) * 256 + (size_t)j * 4);
        }
    };
    auto cpV = [&](int st, int ch) {
        int vt0 = (bk * N_ + ch * 128) >> 4;
        #pragma unroll
        for (int q = 0; q < 4; q++) {
            int slot = q * 256 + tid;
            int dnt = slot >> 7, rem = slot & 127;
            int skt = rem >> 4, w16 = rem & 15;
            CP_ASYNC16(sb + FSTG(st) + 16384u + (uint32_t)slot * 16,
                       vf + ((size_t)(vt0 + skt) * 16 + h) * 512 + dnt * 64 + (size_t)w16 * 4);
        }
    };

    cpQ(); cpK(0, 0); cpV(0, 0); CP_COMMIT();
    cpK(1, 1); cpV(1, 1); CP_COMMIT();

    uint32_t qh[4][4];
    float o[8][4] = {};
    float m0 = -1e30f, m1 = -1e30f, l0 = 0.f, l1 = 0.f;

    for (int ch = 0; ch < 4; ch++) {
        const int st = ch & 1;
        if (ch + 1 < 4) { CP_WAIT1(); } else { CP_WAIT0(); }
        __syncthreads();
        if (ch == 0) {
            #pragma unroll
            for (int kt = 0; kt < 4; kt++) {
                uint4 v = *(const uint4*)(smf + FQ_OFF + (size_t)(((warp * 4 + kt) * 32 + lane) * 4) * 4);
                qh[kt][0] = v.x; qh[kt][1] = v.y; qh[kt][2] = v.z; qh[kt][3] = v.w;
            }
        }
        const char* kb = smf + FSTG(st);
        const char* vb = smf + FSTG(st) + 16384;

        float s[16][4];
        #pragma unroll
        for (int nt = 0; nt < 16; nt++) { s[nt][0] = s[nt][1] = s[nt][2] = s[nt][3] = 0.f; }
        #pragma unroll
        for (int nt = 0; nt < 16; nt++) {
            #pragma unroll
            for (int kt = 0; kt < 4; kt++) {
                uint32_t kh[2];
                uint2 a = *(const uint2*)(kb + (size_t)(((nt * 4 + kt) * 32 + lane) * 2) * 4);
                kh[0] = a.x; kh[1] = a.y;
                mma_f16(s[nt], qh[kt], kh);
            }
        }

        float cm0 = -1e30f, cm1 = -1e30f;
        #pragma unroll
        for (int nt = 0; nt < 16; nt++) {
            cm0 = fmaxf(cm0, fmaxf(s[nt][0], s[nt][1]));
            cm1 = fmaxf(cm1, fmaxf(s[nt][2], s[nt][3]));
        }
        cm0 = fmaxf(cm0, __shfl_xor_sync(0xffffffffu, cm0, 1));
        cm0 = fmaxf(cm0, __shfl_xor_sync(0xffffffffu, cm0, 2));
        cm1 = fmaxf(cm1, __shfl_xor_sync(0xffffffffu, cm1, 1));
        cm1 = fmaxf(cm1, __shfl_xor_sync(0xffffffffu, cm1, 2));
        float nm0 = fmaxf(m0, cm0), nm1 = fmaxf(m1, cm1);
        float al0 = fast_exp(m0 - nm0), al1 = fast_exp(m1 - nm1);
        m0 = nm0; m1 = nm1;
        #pragma unroll
        for (int dnt = 0; dnt < 8; dnt++) {
            o[dnt][0] *= al0; o[dnt][1] *= al0;
            o[dnt][2] *= al1; o[dnt][3] *= al1;
        }
        float ls0 = 0.f, ls1 = 0.f;

        #pragma unroll
        for (int kt = 0; kt < 8; kt++) {
            float p00 = fast_exp(s[2 * kt][0] - m0);
            float p01 = fast_exp(s[2 * kt][1] - m0);
            float p02 = fast_exp(s[2 * kt][2] - m1);
            float p03 = fast_exp(s[2 * kt][3] - m1);
            float p10 = fast_exp(s[2 * kt + 1][0] - m0);
            float p11 = fast_exp(s[2 * kt + 1][1] - m0);
            float p12 = fast_exp(s[2 * kt + 1][2] - m1);
            float p13 = fast_exp(s[2 * kt + 1][3] - m1);
            ls0 += p00 + p01 + p10 + p11;
            ls1 += p02 + p03 + p12 + p13;
            uint32_t ph[4];
            ph[0] = packh2(p00, p01);
            ph[1] = packh2(p02, p03);
            ph[2] = packh2(p10, p11);
            ph[3] = packh2(p12, p13);
            #pragma unroll
            for (int dnt = 0; dnt < 8; dnt++) {
                uint32_t vh[2];
                uint2 a = *(const uint2*)(vb + (size_t)(((dnt * 8 + kt) * 32 + lane) * 2) * 4);
                vh[0] = a.x; vh[1] = a.y;
                mma_f16(o[dnt], ph, vh);
            }
        }
        ls0 += __shfl_xor_sync(0xffffffffu, ls0, 1);
        ls0 += __shfl_xor_sync(0xffffffffu, ls0, 2);
        ls1 += __shfl_xor_sync(0xffffffffu, ls1, 1);
        ls1 += __shfl_xor_sync(0xffffffffu, ls1, 2);
        l0 = l0 * al0 + ls0;
        l1 = l1 * al1 + ls1;

        // refill this stage with chunk ch+2 (all warps done reading it)
        if (ch + 2 < 4) {
            __syncthreads();
            cpK(st, ch + 2); cpV(st, ch + 2); CP_COMMIT();
        }
    }

    __syncthreads();
    uint32_t* sh = (uint32_t*)(smf + FSTG(0));
    float inv0 = 1.0f / l0, inv1 = 1.0f / l1;
    #pragma unroll
    for (int dnt = 0; dnt < 8; dnt++) {
        int kl_ = dnt * 8 + 2 * t;
        int ktl = kl_ >> 4;
        int rk = dnt & 1;
        int baseI = ((warp * 4 + ktl) * 32 + lane) * 4;
        sh[baseI + 2 * rk] = packh2(o[dnt][0] * inv0, o[dnt][1] * inv0);
        sh[baseI + 1 + 2 * rk] = packh2(o[dnt][2] * inv1, o[dnt][3] * inv1);
    }
    __syncthreads();
    #pragma unroll
    for (int q = 0; q < 4; q++) {
        int i = q * 256 + tid;
        int mtl = i >> 7, jj = i & 127;
        size_t gidx = (((size_t)(b * 32 + blockIdx.x * 8 + mtl) * 64) + h * 4) * 128 + (size_t)jj * 4;
        *(uint4*)(Ohi + gidx) = ((const uint4*)sh)[i];
    }
}

// ======================= host orchestration =======================
struct Weights {
    const float *n1g, *n1b, *n2g, *n2b, *pw, *pb, *w1, *b1, *w2, *b2;
};
struct Bufs {
    float *zb;
    uint32_t *qf, *kf, *vf;
    uint32_t *obh, *n2h, *hbh;
    uint32_t *pwh, *w1h, *w2h;
};

static void block_batched(float* resbuf, float* outbuf, int kvxor,
                          const Bufs& B, const Weights& W, const int* guard) {
    lnq_kernel<<<R2_ / 16, 256>>>(resbuf, B.qf, B.kf, B.vf, W.n1g, W.n1b, guard);
    fattn_kernel<<<dim3(4, 8 * NH_), 256, FA_SMEM>>>(B.qf, B.kf, B.vf, kvxor, B.obh, guard);
    gemm_mma<1><<<dim3(C_ / 128, R2_ / 128), 256, GM_SMEM>>>(
        B.obh, B.pwh, outbuf, W.pb, resbuf, nullptr, R2_, C_, C_, guard);
    lnp_kernel<<<R2_ / 16, 256, 32768>>>(outbuf, B.n2h, W.n2g, W.n2b, guard);
    gemm_mma<2><<<dim3(HID_ / 128, R2_ / 128), 256, GM_SMEM>>>(
        B.n2h, B.w1h, nullptr, W.b1, nullptr, B.hbh, R2_, HID_, C_, guard);
    gemm_mma<1><<<dim3(C_ / 128, R2_ / 128), 256, GM_SMEM>>>(
        B.hbh, B.w2h, outbuf, W.b2, outbuf, nullptr, R2_, C_, HID_, guard);
}

extern "C" void kernel_launch(void* const* d_in, const int* in_sizes, int n_in,
                              void* d_out, int out_size) {
    const float* x   = (const float*)d_in[0];
    const float* y   = (const float*)d_in[1];
    Weights W;
    W.n1g = (const float*)d_in[2];  W.n1b = (const float*)d_in[3];
    W.n2g = (const float*)d_in[4];  W.n2b = (const float*)d_in[5];
    W.pw  = (const float*)d_in[6];  W.pb  = (const float*)d_in[7];
    W.w1  = (const float*)d_in[8];  W.b1  = (const float*)d_in[9];
    W.w2  = (const float*)d_in[10]; W.b2  = (const float*)d_in[11];
    const int* flag = (const int*)d_in[12];
    float* out = (float*)d_out;    // 4096 x 1024 = concat(x1, y1)

    Bufs B;
    cudaGetSymbolAddress((void**)&B.zb, g_zb);
    cudaGetSymbolAddress((void**)&B.qf, g_qf);
    cudaGetSymbolAddress((void**)&B.kf, g_kf);
    cudaGetSymbolAddress((void**)&B.vf, g_vf);
    cudaGetSymbolAddress((void**)&B.obh, g_obh);
    cudaGetSymbolAddress((void**)&B.n2h, g_n2h);
    cudaGetSymbolAddress((void**)&B.hbh, g_hbh);
    cudaGetSymbolAddress((void**)&B.pwh, g_pwh);
    cudaGetSymbolAddress((void**)&B.w1h, g_w1h);
    cudaGetSymbolAddress((void**)&B.w2h, g_w2h);

    cudaFuncSetAttribute(gemm_mma<1>, cudaFuncAttributeMaxDynamicSharedMemorySize, GM_SMEM);
    cudaFuncSetAttribute(gemm_mma<2>, cudaFuncAttributeMaxDynamicSharedMemorySize, GM_SMEM);
    cudaFuncSetAttribute(fattn_kernel, cudaFuncAttributeMaxDynamicSharedMemorySize, FA_SMEM);
    cudaFuncSetAttribute(lnp_kernel, cudaFuncAttributeMaxDynamicSharedMemorySize, 32768);

    // weight prep (runs every launch; ~15us)
    pack_weight<<<512, 256>>>(W.pw, B.pwh, C_, C_);
    pack_weight<<<512, 256>>>(W.w1, B.w1h, C_, HID_);
    pack_weight<<<512, 256>>>(W.w2, B.w2h, HID_, C_);

    const size_t bytes = (size_t)R_ * C_ * sizeof(float);
    cudaMemcpyAsync(B.zb, x, bytes, cudaMemcpyDeviceToDevice);
    cudaMemcpyAsync(B.zb + (size_t)R_ * C_, y, bytes, cudaMemcpyDeviceToDevice);

    // x and y self-chains batched as 8 "batches" (x:0-3, y:4-7). Only the
    // FINAL iteration's cross block is live: 4 gated self blocks, then one
    // cross block (kv from opposite half).
    for (int it = 0; it < 4; it++) {
        block_batched(B.zb, B.zb, 0, B, W, flag);
    }
    block_batched(B.zb, out, 4, B, W, nullptr);
}